// round 10
// baseline (speedup 1.0000x reference)
#include <cuda_runtime.h>
#include <cuda_bf16.h>
#include <math.h>

#define N_NODES 50000
#define N_EDGES 400000
#define HEADS 8
#define HID 32
#define F 256            // HEADS*HID
#define NEG 0.2f

// ---------------- scratch (device globals: allocation-free) ----------------
__device__ float    g_h[N_NODES * F];     // X @ W (pre-attention features)
__device__ float    g_asrc[N_NODES * HEADS];
__device__ float    g_adst[N_NODES * HEADS];
__device__ float    g_p[N_NODES * 64];    // [P_a | P_b] node projections
__device__ float    g_wcat[256 * 64];     // [Wp1_a | Wp1_b] packed (fp32 staging)
// bf16 hi/lo split operand storage (packed bf16x2 along k-pairs)
__device__ unsigned g_ah[N_NODES * 64],  g_al[N_NODES * 64];    // x   [N,128]
__device__ unsigned g_xh[N_NODES * 128], g_xl[N_NODES * 128];   // x2  [N,256]
__device__ unsigned g_w1h[64 * 256],  g_w1l[64 * 256];          // W1  [128,256]
__device__ unsigned g_w2h[128 * 256], g_w2l[128 * 256];         // W2  [256,256]
__device__ unsigned g_wch[128 * 64],  g_wcl[128 * 64];          // wcat[256,64]
__device__ int      g_cnt[N_NODES];
__device__ int      g_off[N_NODES + 1];
__device__ int      g_fill[N_NODES];
__device__ int      g_bsum[256];
__device__ int      g_csrc[N_EDGES];

__device__ __forceinline__ float leaky(float x) { return x > 0.f ? x : NEG * x; }

__device__ __forceinline__ unsigned pk(float x, float y) {
    __nv_bfloat162 h = __floats2bfloat162_rn(x, y);
    return *(unsigned*)&h;
}
__device__ __forceinline__ void split2(float x, float y, unsigned& hi, unsigned& lo) {
    float hx = __bfloat162float(__float2bfloat16_rn(x));
    float hy = __bfloat162float(__float2bfloat16_rn(y));
    hi = pk(hx, hy);
    lo = pk(x - hx, y - hy);
}

__device__ __forceinline__ void mma16(float* c,
    unsigned a0, unsigned a1, unsigned a2, unsigned a3,
    unsigned b0, unsigned b1)
{
    asm volatile(
        "mma.sync.aligned.m16n8k16.row.col.f32.bf16.bf16.f32 "
        "{%0,%1,%2,%3}, {%4,%5,%6,%7}, {%8,%9}, {%0,%1,%2,%3};"
        : "+f"(c[0]), "+f"(c[1]), "+f"(c[2]), "+f"(c[3])
        : "r"(a0), "r"(a1), "r"(a2), "r"(a3), "r"(b0), "r"(b1));
}

// ---------------- operand pre-split kernels ----------------
__global__ __launch_bounds__(256) void split_x_kernel(const float* __restrict__ x)
{
    int i = blockIdx.x * blockDim.x + threadIdx.x;       // pair index
    if (i >= N_NODES * 64) return;
    float2 v = *(const float2*)&x[(size_t)i * 2];
    split2(v.x, v.y, g_ah[i], g_al[i]);
}
__global__ __launch_bounds__(256) void split_w_kernel(
    const float* __restrict__ W, unsigned* __restrict__ Wh,
    unsigned* __restrict__ Wl, int KP, int N)
{
    int i = blockIdx.x * blockDim.x + threadIdx.x;
    if (i >= KP * N) return;
    int kp = i / N, n = i - kp * N;
    split2(W[(size_t)(2 * kp) * N + n], W[(size_t)(2 * kp + 1) * N + n], Wh[i], Wl[i]);
}

// ------ 3x bf16 split GEMM on pre-split operands, tile 128x64, BK=16 -------
// 256 threads = 8 warps (4 warp_m x 2 warp_n), warp tile 32x32.
// C = Ah Bh + Al Bh + Ah Bl. Mainloop has ZERO conversion math.
// Optional fused epilogue: per-row attention dots (2 heads per block tile).
__global__ __launch_bounds__(256) void tc_gemm_kernel(
    const unsigned* __restrict__ Ahg, const unsigned* __restrict__ Alg,
    const unsigned* __restrict__ Bhg, const unsigned* __restrict__ Blg,
    float* __restrict__ C, int M, int KP, int ldb, int ldc,
    const float* __restrict__ a_src, const float* __restrict__ a_dst)
{
    __shared__ unsigned Ah[8][132], Al[8][132];
    __shared__ unsigned Bh[8][68],  Bl[8][68];
    __shared__ float sAs[64], sAd[64];

    const int tid = threadIdx.x;
    const int lane = tid & 31;
    const int wid = tid >> 5;
    const int warp_m = wid >> 1;
    const int warp_n = wid & 1;
    const int tig = lane & 3;
    const int grp = lane >> 2;
    const int m0 = blockIdx.x * 128;
    const int n0 = blockIdx.y * 64;

    if (a_src != nullptr && tid < 64) {
        sAs[tid] = a_src[n0 + tid];
        sAd[tid] = a_dst[n0 + tid];
    }

    const int am0 = tid >> 2;             // 0..63
    const int am1 = am0 + 64;             // 64..127
    const int akp = (tid & 3) * 2;        // k-pair base
    const int bn = tid & 63;
    const int bkh = tid >> 6;             // 0..3

    float acc[2][4][4];
#pragma unroll
    for (int mf = 0; mf < 2; ++mf)
#pragma unroll
        for (int nf = 0; nf < 4; ++nf)
#pragma unroll
            for (int j = 0; j < 4; ++j) acc[mf][nf][j] = 0.f;

    for (int k0p = 0; k0p < KP; k0p += 8) {
        // ---- A tile: direct packed loads ----
        {
            uint2 vh = make_uint2(0u, 0u), vl = make_uint2(0u, 0u);
            if (m0 + am0 < M) {
                vh = *(const uint2*)&Ahg[(size_t)(m0 + am0) * KP + k0p + akp];
                vl = *(const uint2*)&Alg[(size_t)(m0 + am0) * KP + k0p + akp];
            }
            Ah[akp][am0] = vh.x; Ah[akp + 1][am0] = vh.y;
            Al[akp][am0] = vl.x; Al[akp + 1][am0] = vl.y;
        }
        {
            uint2 vh = make_uint2(0u, 0u), vl = make_uint2(0u, 0u);
            if (m0 + am1 < M) {
                vh = *(const uint2*)&Ahg[(size_t)(m0 + am1) * KP + k0p + akp];
                vl = *(const uint2*)&Alg[(size_t)(m0 + am1) * KP + k0p + akp];
            }
            Ah[akp][am1] = vh.x; Ah[akp + 1][am1] = vh.y;
            Al[akp][am1] = vl.x; Al[akp + 1][am1] = vl.y;
        }
        // ---- B tile: direct packed loads ----
#pragma unroll
        for (int q = 0; q < 2; ++q) {
            int kp = bkh + q * 4;
            Bh[kp][bn] = Bhg[(size_t)(k0p + kp) * ldb + n0 + bn];
            Bl[kp][bn] = Blg[(size_t)(k0p + kp) * ldb + n0 + bn];
        }
        __syncthreads();

        unsigned ah[2][4], al_[2][4];
#pragma unroll
        for (int mf = 0; mf < 2; ++mf) {
            int mb = warp_m * 32 + mf * 16 + grp;
            ah[mf][0] = Ah[tig][mb];      al_[mf][0] = Al[tig][mb];
            ah[mf][1] = Ah[tig][mb + 8];  al_[mf][1] = Al[tig][mb + 8];
            ah[mf][2] = Ah[tig + 4][mb];      al_[mf][2] = Al[tig + 4][mb];
            ah[mf][3] = Ah[tig + 4][mb + 8];  al_[mf][3] = Al[tig + 4][mb + 8];
        }
#pragma unroll
        for (int nf = 0; nf < 4; ++nf) {
            int n = warp_n * 32 + nf * 8 + grp;
            unsigned bh0 = Bh[tig][n], bh1 = Bh[tig + 4][n];
            unsigned bl0 = Bl[tig][n], bl1 = Bl[tig + 4][n];
#pragma unroll
            for (int mf = 0; mf < 2; ++mf) {
                mma16(acc[mf][nf], ah[mf][0], ah[mf][1], ah[mf][2], ah[mf][3], bh0, bh1);
                mma16(acc[mf][nf], al_[mf][0], al_[mf][1], al_[mf][2], al_[mf][3], bh0, bh1);
                mma16(acc[mf][nf], ah[mf][0], ah[mf][1], ah[mf][2], ah[mf][3], bl0, bl1);
            }
        }
        __syncthreads();
    }

    // ---- store C ----
#pragma unroll
    for (int mf = 0; mf < 2; ++mf) {
        int r0 = m0 + warp_m * 32 + mf * 16 + grp;
        int r1 = r0 + 8;
#pragma unroll
        for (int nf = 0; nf < 4; ++nf) {
            int c = n0 + warp_n * 32 + nf * 8 + tig * 2;
            if (r0 < M)
                *(float2*)&C[(size_t)r0 * ldc + c] = make_float2(acc[mf][nf][0], acc[mf][nf][1]);
            if (r1 < M)
                *(float2*)&C[(size_t)r1 * ldc + c] = make_float2(acc[mf][nf][2], acc[mf][nf][3]);
        }
    }

    // ---- fused attention dots: head = n0/32 + warp_n ----
    if (a_src != nullptr) {
        const int head = (n0 >> 5) + warp_n;
#pragma unroll
        for (int mf = 0; mf < 2; ++mf) {
            float ps0 = 0.f, pd0 = 0.f, ps1 = 0.f, pd1 = 0.f;
#pragma unroll
            for (int nf = 0; nf < 4; ++nf) {
                int cl = warp_n * 32 + nf * 8 + tig * 2;
                float w0s = sAs[cl], w1s = sAs[cl + 1];
                float w0d = sAd[cl], w1d = sAd[cl + 1];
                ps0 += acc[mf][nf][0] * w0s + acc[mf][nf][1] * w1s;
                pd0 += acc[mf][nf][0] * w0d + acc[mf][nf][1] * w1d;
                ps1 += acc[mf][nf][2] * w0s + acc[mf][nf][3] * w1s;
                pd1 += acc[mf][nf][2] * w0d + acc[mf][nf][3] * w1d;
            }
#pragma unroll
            for (int off = 1; off <= 2; off <<= 1) {
                ps0 += __shfl_xor_sync(0xffffffffu, ps0, off);
                pd0 += __shfl_xor_sync(0xffffffffu, pd0, off);
                ps1 += __shfl_xor_sync(0xffffffffu, ps1, off);
                pd1 += __shfl_xor_sync(0xffffffffu, pd1, off);
            }
            if (tig == 0) {
                int r0 = m0 + warp_m * 32 + mf * 16 + grp;
                int r1 = r0 + 8;
                if (r0 < M) { g_asrc[r0 * 8 + head] = ps0; g_adst[r0 * 8 + head] = pd0; }
                if (r1 < M) { g_asrc[r1 * 8 + head] = ps1; g_adst[r1 * 8 + head] = pd1; }
            }
        }
    }
}

// ---------------- CSR build ----------------
__global__ __launch_bounds__(256) void zero_cnt_kernel()
{
    int i = blockIdx.x * blockDim.x + threadIdx.x;
    if (i < N_NODES) g_cnt[i] = 0;
}
__global__ __launch_bounds__(256) void count_kernel(const int* __restrict__ ei)
{
    int e = blockIdx.x * blockDim.x + threadIdx.x;
    if (e < N_EDGES) atomicAdd(&g_cnt[ei[N_EDGES + e]], 1);
}
__global__ __launch_bounds__(256) void scan1_kernel()
{
    __shared__ int sh[256];
    int i = blockIdx.x * 256 + threadIdx.x;
    int v = (i < N_NODES) ? g_cnt[i] : 0;
    sh[threadIdx.x] = v;
    __syncthreads();
#pragma unroll
    for (int off = 1; off < 256; off <<= 1) {
        int t = 0;
        if (threadIdx.x >= off) t = sh[threadIdx.x - off];
        __syncthreads();
        if (threadIdx.x >= off) sh[threadIdx.x] += t;
        __syncthreads();
    }
    if (i < N_NODES) g_off[i + 1] = sh[threadIdx.x];
    if (threadIdx.x == 255) g_bsum[blockIdx.x] = sh[255];
    if (i == 0) g_off[0] = 0;
}
__global__ __launch_bounds__(256) void scan2_kernel(int nblocks)
{
    __shared__ int sh[256];
    int t = threadIdx.x;
    int v = (t < nblocks) ? g_bsum[t] : 0;
    sh[t] = v;
    __syncthreads();
#pragma unroll
    for (int off = 1; off < 256; off <<= 1) {
        int u = 0;
        if (t >= off) u = sh[t - off];
        __syncthreads();
        if (t >= off) sh[t] += u;
        __syncthreads();
    }
    if (t < nblocks) g_bsum[t] = sh[t] - v;    // exclusive
}
__global__ __launch_bounds__(256) void scan3_kernel()
{
    int i = blockIdx.x * 256 + threadIdx.x;
    if (i < N_NODES) {
        int v = g_off[i + 1] + g_bsum[blockIdx.x];
        g_off[i + 1] = v;
        if (i + 1 < N_NODES) g_fill[i + 1] = v;
        if (i == 0) g_fill[0] = 0;
    }
}
__global__ __launch_bounds__(256) void scatter_kernel(const int* __restrict__ ei)
{
    int e = blockIdx.x * blockDim.x + threadIdx.x;
    if (e >= N_EDGES) return;
    int s = ei[e], d = ei[N_EDGES + e];
    int pos = atomicAdd(&g_fill[d], 1);
    g_csrc[pos] = s;
}

// -------- gather attention: one warp per node, fused softmax+agg+relu ------
// Epilogue writes the bf16 hi/lo split of x2 directly (consumed by GEMMs).
__global__ __launch_bounds__(256) void gat_gather_kernel(const float* __restrict__ b)
{
    const int warp = threadIdx.x >> 5, lane = threadIdx.x & 31;
    const int n = blockIdx.x * 8 + warp;
    if (n >= N_NODES) return;
    const unsigned FULL = 0xffffffffu;
    const int h0 = lane >> 3, h1 = 4 + (lane >> 3);

    float myasrc = 0.f, myadst = 0.f;
    if (lane < 8) {
        myasrc = g_asrc[n * 8 + lane];
        myadst = g_adst[n * 8 + lane];
    }
    float4 acc0 = make_float4(0.f, 0.f, 0.f, 0.f);
    float4 acc1 = make_float4(0.f, 0.f, 0.f, 0.f);
    float denom = 0.f;

    const int beg = g_off[n], end = g_off[n + 1];
    for (int i = beg; i < end; ++i) {
        int s = g_csrc[i];
        float w = 0.f;
        if (lane < 8) {
            w = expf(leaky(g_asrc[s * 8 + lane] + myadst));
            denom += w;
        }
        float al0 = __shfl_sync(FULL, w, h0);
        float al1 = __shfl_sync(FULL, w, h1);
        float4 v0 = *(const float4*)&g_h[(size_t)s * 256 + lane * 4];
        float4 v1 = *(const float4*)&g_h[(size_t)s * 256 + 128 + lane * 4];
        acc0.x += al0 * v0.x; acc0.y += al0 * v0.y;
        acc0.z += al0 * v0.z; acc0.w += al0 * v0.w;
        acc1.x += al1 * v1.x; acc1.y += al1 * v1.y;
        acc1.z += al1 * v1.z; acc1.w += al1 * v1.w;
    }
    // self loop
    {
        float w = 0.f;
        if (lane < 8) {
            w = expf(leaky(myasrc + myadst));
            denom += w;
        }
        float al0 = __shfl_sync(FULL, w, h0);
        float al1 = __shfl_sync(FULL, w, h1);
        float4 v0 = *(const float4*)&g_h[(size_t)n * 256 + lane * 4];
        float4 v1 = *(const float4*)&g_h[(size_t)n * 256 + 128 + lane * 4];
        acc0.x += al0 * v0.x; acc0.y += al0 * v0.y;
        acc0.z += al0 * v0.z; acc0.w += al0 * v0.w;
        acc1.x += al1 * v1.x; acc1.y += al1 * v1.y;
        acc1.z += al1 * v1.z; acc1.w += al1 * v1.w;
    }
    float inv0 = 1.f / __shfl_sync(FULL, denom, h0);
    float inv1 = 1.f / __shfl_sync(FULL, denom, h1);
    float4 bb0 = *(const float4*)&b[lane * 4];
    float4 bb1 = *(const float4*)&b[128 + lane * 4];
    float4 o0, o1;
    o0.x = fmaxf(acc0.x * inv0 + bb0.x, 0.f);
    o0.y = fmaxf(acc0.y * inv0 + bb0.y, 0.f);
    o0.z = fmaxf(acc0.z * inv0 + bb0.z, 0.f);
    o0.w = fmaxf(acc0.w * inv0 + bb0.w, 0.f);
    o1.x = fmaxf(acc1.x * inv1 + bb1.x, 0.f);
    o1.y = fmaxf(acc1.y * inv1 + bb1.y, 0.f);
    o1.z = fmaxf(acc1.z * inv1 + bb1.z, 0.f);
    o1.w = fmaxf(acc1.w * inv1 + bb1.w, 0.f);

    // write split x2 (k-pairs): cols lane*4..+3 and 128+lane*4..+3
    unsigned h, l;
    size_t base = (size_t)n * 128;
    split2(o0.x, o0.y, h, l); g_xh[base + lane * 2]     = h; g_xl[base + lane * 2]     = l;
    split2(o0.z, o0.w, h, l); g_xh[base + lane * 2 + 1] = h; g_xl[base + lane * 2 + 1] = l;
    split2(o1.x, o1.y, h, l); g_xh[base + 64 + lane * 2]     = h; g_xl[base + 64 + lane * 2]     = l;
    split2(o1.z, o1.w, h, l); g_xh[base + 64 + lane * 2 + 1] = h; g_xl[base + 64 + lane * 2 + 1] = l;
}

// ---------------- pack Wcat = [Wp1_a | Wp1_b] : [256 x 64] ----------------
__global__ __launch_bounds__(256) void pack_wcat_kernel(const float* __restrict__ Wp1)
{
    int i = blockIdx.x * blockDim.x + threadIdx.x;
    if (i >= 256 * 64) return;
    int k = i >> 6, j = i & 63;
    g_wcat[i] = (j < 32) ? Wp1[k * 32 + j] : Wp1[(256 + k) * 32 + (j - 32)];
}

// ---------------- edge predictor: emb MLP + combine (fp32) ----------------
__global__ __launch_bounds__(128) void edge_pred_kernel(
    const int* __restrict__ ei, const float* __restrict__ edge_attr,
    const float* __restrict__ Wm1, const float* __restrict__ bm1,
    const float* __restrict__ Wm2, const float* __restrict__ bm2,
    const float* __restrict__ Wp1, const float* __restrict__ bp1,
    const float* __restrict__ Wp2, const float* __restrict__ bp2,
    float* __restrict__ out)
{
    __shared__ float sEA[64 * 33];
    __shared__ float sT1[64 * 33];
    __shared__ float sW[3072];          // Wm1 | Wm2 | Wp1_c
    __shared__ int   sRow[64], sCol[64];
    __shared__ float sB[64];            // bm1 | bm2

    const int tid = threadIdx.x;
    const int tx = tid & 7;
    const int ey = tid >> 3;
    const int e0 = blockIdx.x * 64;

    if (tid < 64) {
        sRow[tid] = ei[e0 + tid];
        sCol[tid] = ei[N_EDGES + e0 + tid];
    }
    for (int i = tid; i < 3072; i += 128)
        sW[i] = (i < 1024) ? Wm1[i]
              : (i < 2048) ? Wm2[i - 1024]
                           : Wp1[512 * 32 + (i - 2048)];
    if (tid < 32) { sB[tid] = bm1[tid]; sB[32 + tid] = bm2[tid]; }
    for (int f = tid; f < 64 * 8; f += 128) {
        int e = f >> 3, q = f & 7;
        float4 v = *(const float4*)&edge_attr[(size_t)(e0 + e) * 32 + q * 4];
        float* p = &sEA[e * 33 + q * 4];
        p[0] = v.x; p[1] = v.y; p[2] = v.z; p[3] = v.w;
    }
    __syncthreads();

    // layer 1: T1 = relu(EA @ Wm1 + bm1)
    {
        float acc[4][4];
#pragma unroll
        for (int i = 0; i < 4; ++i)
#pragma unroll
            for (int j = 0; j < 4; ++j) acc[i][j] = 0.f;
#pragma unroll
        for (int k = 0; k < 32; ++k) {
            float4 w = *(const float4*)&sW[k * 32 + tx * 4];
#pragma unroll
            for (int i = 0; i < 4; ++i) {
                float a = sEA[(ey * 4 + i) * 33 + k];
                acc[i][0] += a * w.x; acc[i][1] += a * w.y;
                acc[i][2] += a * w.z; acc[i][3] += a * w.w;
            }
        }
#pragma unroll
        for (int i = 0; i < 4; ++i)
#pragma unroll
            for (int j = 0; j < 4; ++j) {
                float v = acc[i][j] + sB[tx * 4 + j];
                sT1[(ey * 4 + i) * 33 + tx * 4 + j] = v > 0.f ? v : 0.f;
            }
    }
    __syncthreads();
    // layer 2: EMB = relu(T1 @ Wm2 + bm2) -> sEA (reuse)
    {
        float acc[4][4];
#pragma unroll
        for (int i = 0; i < 4; ++i)
#pragma unroll
            for (int j = 0; j < 4; ++j) acc[i][j] = 0.f;
#pragma unroll
        for (int k = 0; k < 32; ++k) {
            float4 w = *(const float4*)&sW[1024 + k * 32 + tx * 4];
#pragma unroll
            for (int i = 0; i < 4; ++i) {
                float a = sT1[(ey * 4 + i) * 33 + k];
                acc[i][0] += a * w.x; acc[i][1] += a * w.y;
                acc[i][2] += a * w.z; acc[i][3] += a * w.w;
            }
        }
        __syncthreads();
#pragma unroll
        for (int i = 0; i < 4; ++i)
#pragma unroll
            for (int j = 0; j < 4; ++j) {
                float v = acc[i][j] + sB[32 + tx * 4 + j];
                sEA[(ey * 4 + i) * 33 + tx * 4 + j] = v > 0.f ? v : 0.f;
            }
    }
    __syncthreads();
    // layer 3: acc = EMB @ Wp1_c
    float acc[4][4];
#pragma unroll
    for (int i = 0; i < 4; ++i)
#pragma unroll
        for (int j = 0; j < 4; ++j) acc[i][j] = 0.f;
#pragma unroll
    for (int k = 0; k < 32; ++k) {
        float4 w = *(const float4*)&sW[2048 + k * 32 + tx * 4];
#pragma unroll
        for (int i = 0; i < 4; ++i) {
            float a = sEA[(ey * 4 + i) * 33 + k];
            acc[i][0] += a * w.x; acc[i][1] += a * w.y;
            acc[i][2] += a * w.z; acc[i][3] += a * w.w;
        }
    }

    // epilogue: pre = acc + P_a[row] + P_b[col] + bp1; out = relu(pre)@Wp2 + bp2
    float4 bp = *(const float4*)&bp1[tx * 4];
    float4 wp = *(const float4*)&Wp2[tx * 4];
    float bias2 = bp2[0];
#pragma unroll
    for (int i = 0; i < 4; ++i) {
        int e = ey * 4 + i;
        int r = sRow[e], c = sCol[e];
        float4 pa = *(const float4*)&g_p[(size_t)r * 64 + tx * 4];
        float4 pb = *(const float4*)&g_p[(size_t)c * 64 + 32 + tx * 4];
        float h0 = acc[i][0] + pa.x + pb.x + bp.x; h0 = h0 > 0.f ? h0 : 0.f;
        float h1 = acc[i][1] + pa.y + pb.y + bp.y; h1 = h1 > 0.f ? h1 : 0.f;
        float h2 = acc[i][2] + pa.z + pb.z + bp.z; h2 = h2 > 0.f ? h2 : 0.f;
        float h3 = acc[i][3] + pa.w + pb.w + bp.w; h3 = h3 > 0.f ? h3 : 0.f;
        float p = h0 * wp.x + h1 * wp.y + h2 * wp.z + h3 * wp.w;
        p += __shfl_down_sync(0xffffffffu, p, 4, 8);
        p += __shfl_down_sync(0xffffffffu, p, 2, 8);
        p += __shfl_down_sync(0xffffffffu, p, 1, 8);
        if (tx == 0) out[e0 + e] = p + bias2;
    }
}

// ---------------- host ----------------
extern "C" void kernel_launch(void* const* d_in, const int* in_sizes, int n_in,
                              void* d_out, int out_size)
{
    const float* x   = (const float*)d_in[0];
    const int*   ei  = (const int*)d_in[1];
    const float* ea  = (const float*)d_in[2];
    const float* W1  = (const float*)d_in[3];
    const float* as1 = (const float*)d_in[4];
    const float* ad1 = (const float*)d_in[5];
    const float* b1  = (const float*)d_in[6];
    const float* W2  = (const float*)d_in[7];
    const float* as2 = (const float*)d_in[8];
    const float* ad2 = (const float*)d_in[9];
    const float* b2  = (const float*)d_in[10];
    const float* Wm1 = (const float*)d_in[11];
    const float* bm1 = (const float*)d_in[12];
    const float* Wm2 = (const float*)d_in[13];
    const float* bm2 = (const float*)d_in[14];
    const float* Wp1 = (const float*)d_in[15];
    const float* bp1 = (const float*)d_in[16];
    const float* Wp2 = (const float*)d_in[17];
    const float* bp2 = (const float*)d_in[18];
    float* out = (float*)d_out;

    float *ph = nullptr, *pw = nullptr, *pp = nullptr;
    unsigned *pah, *pal, *pxh, *pxl, *pw1h, *pw1l, *pw2h, *pw2l, *pwch, *pwcl;
    cudaGetSymbolAddress((void**)&ph, g_h);
    cudaGetSymbolAddress((void**)&pw, g_wcat);
    cudaGetSymbolAddress((void**)&pp, g_p);
    cudaGetSymbolAddress((void**)&pah, g_ah);
    cudaGetSymbolAddress((void**)&pal, g_al);
    cudaGetSymbolAddress((void**)&pxh, g_xh);
    cudaGetSymbolAddress((void**)&pxl, g_xl);
    cudaGetSymbolAddress((void**)&pw1h, g_w1h);
    cudaGetSymbolAddress((void**)&pw1l, g_w1l);
    cudaGetSymbolAddress((void**)&pw2h, g_w2h);
    cudaGetSymbolAddress((void**)&pw2l, g_w2l);
    cudaGetSymbolAddress((void**)&pwch, g_wch);
    cudaGetSymbolAddress((void**)&pwcl, g_wcl);

    const int EB  = (N_EDGES + 255) / 256;
    const int NB  = (N_NODES + 255) / 256;
    const int NWB = (N_NODES + 7) / 8;

    // ---- CSR build (once; reused by both layers) ----
    zero_cnt_kernel<<<NB, 256>>>();
    count_kernel<<<EB, 256>>>(ei);
    scan1_kernel<<<NB, 256>>>();
    scan2_kernel<<<1, 256>>>(NB);
    scan3_kernel<<<NB, 256>>>();
    scatter_kernel<<<EB, 256>>>(ei);

    // ---- operand pre-splits ----
    split_x_kernel<<<(N_NODES * 64 + 255) / 256, 256>>>(x);
    split_w_kernel<<<(64 * 256 + 255) / 256, 256>>>(W1, pw1h, pw1l, 64, 256);
    split_w_kernel<<<(128 * 256 + 255) / 256, 256>>>(W2, pw2h, pw2l, 128, 256);
    pack_wcat_kernel<<<64, 256>>>(Wp1);
    split_w_kernel<<<(128 * 64 + 255) / 256, 256>>>(pw, pwch, pwcl, 128, 64);

    for (int layer = 0; layer < 2; ++layer) {
        const unsigned* Ahg = layer ? pxh : pah;
        const unsigned* Alg = layer ? pxl : pal;
        const unsigned* Bhg = layer ? pw2h : pw1h;
        const unsigned* Blg = layer ? pw2l : pw1l;
        const int       KP  = layer ? 128 : 64;
        const float*    as_ = layer ? as2 : as1;
        const float*    ad_ = layer ? ad2 : ad1;
        const float*    b_  = layer ? b2 : b1;

        tc_gemm_kernel<<<dim3(391, 4), 256>>>(Ahg, Alg, Bhg, Blg, ph,
                                              N_NODES, KP, 256, 256, as_, ad_);
        gat_gather_kernel<<<NWB, 256>>>(b_);
    }
    tc_gemm_kernel<<<dim3(391, 1), 256>>>(pxh, pxl, pwch, pwcl, pp,
                                          N_NODES, 128, 64, 64, nullptr, nullptr);
    edge_pred_kernel<<<N_EDGES / 64, 128>>>(ei, ea,
                                            Wm1, bm1, Wm2, bm2,
                                            Wp1, bp1, Wp2, bp2, out);
}

// round 11
// speedup vs baseline: 1.0201x; 1.0201x over previous
#include <cuda_runtime.h>
#include <cuda_bf16.h>
#include <math.h>

#define N_NODES 50000
#define N_EDGES 400000
#define HEADS 8
#define HID 32
#define F 256            // HEADS*HID
#define NEG 0.2f

// ---------------- scratch (device globals: allocation-free) ----------------
__device__ float g_h[N_NODES * F];        // X @ W (pre-attention features)
__device__ float g_x[N_NODES * F];        // layer output
__device__ float g_asrc[N_NODES * HEADS];
__device__ float g_adst[N_NODES * HEADS];
__device__ float g_p[N_NODES * 64];       // [P_a | P_b] node projections
__device__ float g_wcat[256 * 64];        // [Wp1_a | Wp1_b] packed
__device__ int   g_cnt[N_NODES];
__device__ int   g_off[N_NODES + 1];
__device__ int   g_fill[N_NODES];
__device__ int   g_bsum[256];
__device__ int   g_csrc[N_EDGES];

__device__ __forceinline__ float leaky(float x) { return x > 0.f ? x : NEG * x; }

// rn hi/lo split, packed: identical semantics to rounds 9's split2, fewer ops
__device__ __forceinline__ void split2(float x, float y, unsigned& hi, unsigned& lo) {
    __nv_bfloat162 h2 = __floats2bfloat162_rn(x, y);       // one packed cvt
    unsigned hu = *(unsigned*)&h2;
    float hx = __uint_as_float(hu << 16);                  // bf16(x) as f32
    float hy = __uint_as_float(hu & 0xffff0000u);          // bf16(y) as f32
    __nv_bfloat162 l2 = __floats2bfloat162_rn(x - hx, y - hy);
    hi = hu;
    lo = *(unsigned*)&l2;
}

__device__ __forceinline__ void mma16(float* c,
    unsigned a0, unsigned a1, unsigned a2, unsigned a3,
    unsigned b0, unsigned b1)
{
    asm volatile(
        "mma.sync.aligned.m16n8k16.row.col.f32.bf16.bf16.f32 "
        "{%0,%1,%2,%3}, {%4,%5,%6,%7}, {%8,%9}, {%0,%1,%2,%3};"
        : "+f"(c[0]), "+f"(c[1]), "+f"(c[2]), "+f"(c[3])
        : "r"(a0), "r"(a1), "r"(a2), "r"(a3), "r"(b0), "r"(b1));
}

// ------ 3x bf16 split GEMM: C[M x N] = A[M x K] @ B[K x N], tile 128x64 ----
// 256 threads = 8 warps (4 warp_m x 2 warp_n), warp tile 32x32, BK=16.
// Smem layout interleaves hi/lo with permuted k-pairs:
//   col(kp, sel) = 4*(kp&3) + 2*(kp>>2) + sel   (16 words per row)
// so one LDS.128 at col 4*tig yields {hi[tig], lo[tig], hi[tig+4], lo[tig+4]}.
// C = Ah Bh + Al Bh + Ah Bl.
__global__ __launch_bounds__(256) void tc_gemm_kernel(
    const float* __restrict__ A, const float* __restrict__ B,
    float* __restrict__ C, int M, int K, int ldb, int ldc,
    const float* __restrict__ a_src, const float* __restrict__ a_dst)
{
    __shared__ __align__(16) unsigned As[128][16];
    __shared__ __align__(16) unsigned Bs[64][16];
    __shared__ float sAs[64], sAd[64];

    const int tid = threadIdx.x;
    const int lane = tid & 31;
    const int wid = tid >> 5;
    const int warp_m = wid >> 1;          // rows warp_m*32
    const int warp_n = wid & 1;           // cols warp_n*32
    const int tig = lane & 3;
    const int grp = lane >> 2;
    const int m0 = blockIdx.x * 128;
    const int n0 = blockIdx.y * 64;

    if (a_src != nullptr && tid < 64) {
        sAs[tid] = a_src[n0 + tid];
        sAd[tid] = a_dst[n0 + tid];
    }

    // A loader: rows am0/am1, k-pairs akp & akp+1 (4 consecutive k)
    const int am0 = tid >> 2;             // 0..63
    const int am1 = am0 + 64;             // 64..127
    const int akp = (tid & 3) * 2;
    const int ca0 = 4 * (akp & 3) + 2 * (akp >> 2);
    const int ca1 = 4 * ((akp + 1) & 3) + 2 * ((akp + 1) >> 2);
    // B loader: row bn, k-pairs bkh and bkh+4
    const int bn = tid & 63;
    const int bkh = tid >> 6;             // 0..3
    const int cb0 = 4 * bkh;              // kp = bkh
    const int cb1 = 4 * bkh + 2;          // kp = bkh+4

    float acc[2][4][4];
#pragma unroll
    for (int mf = 0; mf < 2; ++mf)
#pragma unroll
        for (int nf = 0; nf < 4; ++nf)
#pragma unroll
            for (int j = 0; j < 4; ++j) acc[mf][nf][j] = 0.f;

    for (int k0 = 0; k0 < K; k0 += 16) {
        // ---- A tile ----
        {
            float4 v = make_float4(0.f, 0.f, 0.f, 0.f);
            if (m0 + am0 < M) v = *(const float4*)&A[(size_t)(m0 + am0) * K + k0 + akp * 2];
            unsigned h, l;
            split2(v.x, v.y, h, l); *(uint2*)&As[am0][ca0] = make_uint2(h, l);
            split2(v.z, v.w, h, l); *(uint2*)&As[am0][ca1] = make_uint2(h, l);
        }
        {
            float4 v = make_float4(0.f, 0.f, 0.f, 0.f);
            if (m0 + am1 < M) v = *(const float4*)&A[(size_t)(m0 + am1) * K + k0 + akp * 2];
            unsigned h, l;
            split2(v.x, v.y, h, l); *(uint2*)&As[am1][ca0] = make_uint2(h, l);
            split2(v.z, v.w, h, l); *(uint2*)&As[am1][ca1] = make_uint2(h, l);
        }
        // ---- B tile ----
        {
            float f0 = B[(size_t)(k0 + 2 * bkh) * ldb + n0 + bn];
            float f1 = B[(size_t)(k0 + 2 * bkh + 1) * ldb + n0 + bn];
            unsigned h, l;
            split2(f0, f1, h, l); *(uint2*)&Bs[bn][cb0] = make_uint2(h, l);
            int kp = bkh + 4;
            f0 = B[(size_t)(k0 + 2 * kp) * ldb + n0 + bn];
            f1 = B[(size_t)(k0 + 2 * kp + 1) * ldb + n0 + bn];
            split2(f0, f1, h, l); *(uint2*)&Bs[bn][cb1] = make_uint2(h, l);
        }
        __syncthreads();

        // ---- fragments: one LDS.128 per (row, hi+lo, k and k+4) ----
        unsigned ah[2][4], al_[2][4];
#pragma unroll
        for (int mf = 0; mf < 2; ++mf) {
            int mb = warp_m * 32 + mf * 16 + grp;
            uint4 va = *(const uint4*)&As[mb][4 * tig];
            uint4 vb = *(const uint4*)&As[mb + 8][4 * tig];
            ah[mf][0] = va.x; al_[mf][0] = va.y;
            ah[mf][2] = va.z; al_[mf][2] = va.w;
            ah[mf][1] = vb.x; al_[mf][1] = vb.y;
            ah[mf][3] = vb.z; al_[mf][3] = vb.w;
        }
#pragma unroll
        for (int nf = 0; nf < 4; ++nf) {
            int n = warp_n * 32 + nf * 8 + grp;
            uint4 vB = *(const uint4*)&Bs[n][4 * tig];
            unsigned bh0 = vB.x, bl0 = vB.y, bh1 = vB.z, bl1 = vB.w;
#pragma unroll
            for (int mf = 0; mf < 2; ++mf) {
                mma16(acc[mf][nf], ah[mf][0], ah[mf][1], ah[mf][2], ah[mf][3], bh0, bh1);
                mma16(acc[mf][nf], al_[mf][0], al_[mf][1], al_[mf][2], al_[mf][3], bh0, bh1);
                mma16(acc[mf][nf], ah[mf][0], ah[mf][1], ah[mf][2], ah[mf][3], bl0, bl1);
            }
        }
        __syncthreads();
    }

    // ---- store C ----
#pragma unroll
    for (int mf = 0; mf < 2; ++mf) {
        int r0 = m0 + warp_m * 32 + mf * 16 + grp;
        int r1 = r0 + 8;
#pragma unroll
        for (int nf = 0; nf < 4; ++nf) {
            int c = n0 + warp_n * 32 + nf * 8 + tig * 2;
            if (r0 < M)
                *(float2*)&C[(size_t)r0 * ldc + c] = make_float2(acc[mf][nf][0], acc[mf][nf][1]);
            if (r1 < M)
                *(float2*)&C[(size_t)r1 * ldc + c] = make_float2(acc[mf][nf][2], acc[mf][nf][3]);
        }
    }

    // ---- fused attention dots: head = n0/32 + warp_n ----
    if (a_src != nullptr) {
        const int head = (n0 >> 5) + warp_n;
#pragma unroll
        for (int mf = 0; mf < 2; ++mf) {
            float ps0 = 0.f, pd0 = 0.f, ps1 = 0.f, pd1 = 0.f;
#pragma unroll
            for (int nf = 0; nf < 4; ++nf) {
                int cl = warp_n * 32 + nf * 8 + tig * 2;
                float w0s = sAs[cl], w1s = sAs[cl + 1];
                float w0d = sAd[cl], w1d = sAd[cl + 1];
                ps0 += acc[mf][nf][0] * w0s + acc[mf][nf][1] * w1s;
                pd0 += acc[mf][nf][0] * w0d + acc[mf][nf][1] * w1d;
                ps1 += acc[mf][nf][2] * w0s + acc[mf][nf][3] * w1s;
                pd1 += acc[mf][nf][2] * w0d + acc[mf][nf][3] * w1d;
            }
#pragma unroll
            for (int off = 1; off <= 2; off <<= 1) {
                ps0 += __shfl_xor_sync(0xffffffffu, ps0, off);
                pd0 += __shfl_xor_sync(0xffffffffu, pd0, off);
                ps1 += __shfl_xor_sync(0xffffffffu, ps1, off);
                pd1 += __shfl_xor_sync(0xffffffffu, pd1, off);
            }
            if (tig == 0) {
                int r0 = m0 + warp_m * 32 + mf * 16 + grp;
                int r1 = r0 + 8;
                if (r0 < M) { g_asrc[r0 * 8 + head] = ps0; g_adst[r0 * 8 + head] = pd0; }
                if (r1 < M) { g_asrc[r1 * 8 + head] = ps1; g_adst[r1 * 8 + head] = pd1; }
            }
        }
    }
}

// ---------------- CSR build ----------------
__global__ __launch_bounds__(256) void zero_cnt_kernel()
{
    int i = blockIdx.x * blockDim.x + threadIdx.x;
    if (i < N_NODES) g_cnt[i] = 0;
}
__global__ __launch_bounds__(256) void count_kernel(const int* __restrict__ ei)
{
    int e = blockIdx.x * blockDim.x + threadIdx.x;
    if (e < N_EDGES) atomicAdd(&g_cnt[ei[N_EDGES + e]], 1);
}
__global__ __launch_bounds__(256) void scan1_kernel()
{
    __shared__ int sh[256];
    int i = blockIdx.x * 256 + threadIdx.x;
    int v = (i < N_NODES) ? g_cnt[i] : 0;
    sh[threadIdx.x] = v;
    __syncthreads();
#pragma unroll
    for (int off = 1; off < 256; off <<= 1) {
        int t = 0;
        if (threadIdx.x >= off) t = sh[threadIdx.x - off];
        __syncthreads();
        if (threadIdx.x >= off) sh[threadIdx.x] += t;
        __syncthreads();
    }
    if (i < N_NODES) g_off[i + 1] = sh[threadIdx.x];
    if (threadIdx.x == 255) g_bsum[blockIdx.x] = sh[255];
    if (i == 0) g_off[0] = 0;
}
__global__ __launch_bounds__(256) void scan2_kernel(int nblocks)
{
    __shared__ int sh[256];
    int t = threadIdx.x;
    int v = (t < nblocks) ? g_bsum[t] : 0;
    sh[t] = v;
    __syncthreads();
#pragma unroll
    for (int off = 1; off < 256; off <<= 1) {
        int u = 0;
        if (t >= off) u = sh[t - off];
        __syncthreads();
        if (t >= off) sh[t] += u;
        __syncthreads();
    }
    if (t < nblocks) g_bsum[t] = sh[t] - v;    // exclusive
}
__global__ __launch_bounds__(256) void scan3_kernel()
{
    int i = blockIdx.x * 256 + threadIdx.x;
    if (i < N_NODES) {
        int v = g_off[i + 1] + g_bsum[blockIdx.x];
        g_off[i + 1] = v;
        if (i + 1 < N_NODES) g_fill[i + 1] = v;
        if (i == 0) g_fill[0] = 0;
    }
}
__global__ __launch_bounds__(256) void scatter_kernel(const int* __restrict__ ei)
{
    int e = blockIdx.x * blockDim.x + threadIdx.x;
    if (e >= N_EDGES) return;
    int s = ei[e], d = ei[N_EDGES + e];
    int pos = atomicAdd(&g_fill[d], 1);
    g_csrc[pos] = s;
}

// -------- gather attention: one warp per node, fused softmax+agg+relu ------
__global__ __launch_bounds__(256) void gat_gather_kernel(const float* __restrict__ b)
{
    const int warp = threadIdx.x >> 5, lane = threadIdx.x & 31;
    const int n = blockIdx.x * 8 + warp;
    if (n >= N_NODES) return;
    const unsigned FULL = 0xffffffffu;
    const int h0 = lane >> 3, h1 = 4 + (lane >> 3);

    float myasrc = 0.f, myadst = 0.f;
    if (lane < 8) {
        myasrc = g_asrc[n * 8 + lane];
        myadst = g_adst[n * 8 + lane];
    }
    float4 acc0 = make_float4(0.f, 0.f, 0.f, 0.f);
    float4 acc1 = make_float4(0.f, 0.f, 0.f, 0.f);
    float denom = 0.f;

    const int beg = g_off[n], end = g_off[n + 1];
    for (int i = beg; i < end; ++i) {
        int s = g_csrc[i];
        float w = 0.f;
        if (lane < 8) {
            w = expf(leaky(g_asrc[s * 8 + lane] + myadst));
            denom += w;
        }
        float al0 = __shfl_sync(FULL, w, h0);
        float al1 = __shfl_sync(FULL, w, h1);
        float4 v0 = *(const float4*)&g_h[(size_t)s * 256 + lane * 4];
        float4 v1 = *(const float4*)&g_h[(size_t)s * 256 + 128 + lane * 4];
        acc0.x += al0 * v0.x; acc0.y += al0 * v0.y;
        acc0.z += al0 * v0.z; acc0.w += al0 * v0.w;
        acc1.x += al1 * v1.x; acc1.y += al1 * v1.y;
        acc1.z += al1 * v1.z; acc1.w += al1 * v1.w;
    }
    // self loop
    {
        float w = 0.f;
        if (lane < 8) {
            w = expf(leaky(myasrc + myadst));
            denom += w;
        }
        float al0 = __shfl_sync(FULL, w, h0);
        float al1 = __shfl_sync(FULL, w, h1);
        float4 v0 = *(const float4*)&g_h[(size_t)n * 256 + lane * 4];
        float4 v1 = *(const float4*)&g_h[(size_t)n * 256 + 128 + lane * 4];
        acc0.x += al0 * v0.x; acc0.y += al0 * v0.y;
        acc0.z += al0 * v0.z; acc0.w += al0 * v0.w;
        acc1.x += al1 * v1.x; acc1.y += al1 * v1.y;
        acc1.z += al1 * v1.z; acc1.w += al1 * v1.w;
    }
    float inv0 = 1.f / __shfl_sync(FULL, denom, h0);
    float inv1 = 1.f / __shfl_sync(FULL, denom, h1);
    float4 bb0 = *(const float4*)&b[lane * 4];
    float4 bb1 = *(const float4*)&b[128 + lane * 4];
    float4 o0, o1;
    o0.x = fmaxf(acc0.x * inv0 + bb0.x, 0.f);
    o0.y = fmaxf(acc0.y * inv0 + bb0.y, 0.f);
    o0.z = fmaxf(acc0.z * inv0 + bb0.z, 0.f);
    o0.w = fmaxf(acc0.w * inv0 + bb0.w, 0.f);
    o1.x = fmaxf(acc1.x * inv1 + bb1.x, 0.f);
    o1.y = fmaxf(acc1.y * inv1 + bb1.y, 0.f);
    o1.z = fmaxf(acc1.z * inv1 + bb1.z, 0.f);
    o1.w = fmaxf(acc1.w * inv1 + bb1.w, 0.f);
    *(float4*)&g_x[(size_t)n * 256 + lane * 4] = o0;
    *(float4*)&g_x[(size_t)n * 256 + 128 + lane * 4] = o1;
}

// ---------------- pack Wcat = [Wp1_a | Wp1_b] : [256 x 64] ----------------
__global__ __launch_bounds__(256) void pack_wcat_kernel(const float* __restrict__ Wp1)
{
    int i = blockIdx.x * blockDim.x + threadIdx.x;
    if (i >= 256 * 64) return;
    int k = i >> 6, j = i & 63;
    g_wcat[i] = (j < 32) ? Wp1[k * 32 + j] : Wp1[(256 + k) * 32 + (j - 32)];
}

// ---------------- edge predictor: emb MLP + combine (fp32) ----------------
__global__ __launch_bounds__(128) void edge_pred_kernel(
    const int* __restrict__ ei, const float* __restrict__ edge_attr,
    const float* __restrict__ Wm1, const float* __restrict__ bm1,
    const float* __restrict__ Wm2, const float* __restrict__ bm2,
    const float* __restrict__ Wp1, const float* __restrict__ bp1,
    const float* __restrict__ Wp2, const float* __restrict__ bp2,
    float* __restrict__ out)
{
    __shared__ float sEA[64 * 33];
    __shared__ float sT1[64 * 33];
    __shared__ float sW[3072];          // Wm1 | Wm2 | Wp1_c
    __shared__ int   sRow[64], sCol[64];
    __shared__ float sB[64];            // bm1 | bm2

    const int tid = threadIdx.x;
    const int tx = tid & 7;
    const int ey = tid >> 3;
    const int e0 = blockIdx.x * 64;

    if (tid < 64) {
        sRow[tid] = ei[e0 + tid];
        sCol[tid] = ei[N_EDGES + e0 + tid];
    }
    for (int i = tid; i < 3072; i += 128)
        sW[i] = (i < 1024) ? Wm1[i]
              : (i < 2048) ? Wm2[i - 1024]
                           : Wp1[512 * 32 + (i - 2048)];
    if (tid < 32) { sB[tid] = bm1[tid]; sB[32 + tid] = bm2[tid]; }
    for (int f = tid; f < 64 * 8; f += 128) {
        int e = f >> 3, q = f & 7;
        float4 v = *(const float4*)&edge_attr[(size_t)(e0 + e) * 32 + q * 4];
        float* p = &sEA[e * 33 + q * 4];
        p[0] = v.x; p[1] = v.y; p[2] = v.z; p[3] = v.w;
    }
    __syncthreads();

    // layer 1: T1 = relu(EA @ Wm1 + bm1)
    {
        float acc[4][4];
#pragma unroll
        for (int i = 0; i < 4; ++i)
#pragma unroll
            for (int j = 0; j < 4; ++j) acc[i][j] = 0.f;
#pragma unroll
        for (int k = 0; k < 32; ++k) {
            float4 w = *(const float4*)&sW[k * 32 + tx * 4];
#pragma unroll
            for (int i = 0; i < 4; ++i) {
                float a = sEA[(ey * 4 + i) * 33 + k];
                acc[i][0] += a * w.x; acc[i][1] += a * w.y;
                acc[i][2] += a * w.z; acc[i][3] += a * w.w;
            }
        }
#pragma unroll
        for (int i = 0; i < 4; ++i)
#pragma unroll
            for (int j = 0; j < 4; ++j) {
                float v = acc[i][j] + sB[tx * 4 + j];
                sT1[(ey * 4 + i) * 33 + tx * 4 + j] = v > 0.f ? v : 0.f;
            }
    }
    __syncthreads();
    // layer 2: EMB = relu(T1 @ Wm2 + bm2) -> sEA (reuse)
    {
        float acc[4][4];
#pragma unroll
        for (int i = 0; i < 4; ++i)
#pragma unroll
            for (int j = 0; j < 4; ++j) acc[i][j] = 0.f;
#pragma unroll
        for (int k = 0; k < 32; ++k) {
            float4 w = *(const float4*)&sW[1024 + k * 32 + tx * 4];
#pragma unroll
            for (int i = 0; i < 4; ++i) {
                float a = sT1[(ey * 4 + i) * 33 + k];
                acc[i][0] += a * w.x; acc[i][1] += a * w.y;
                acc[i][2] += a * w.z; acc[i][3] += a * w.w;
            }
        }
        __syncthreads();
#pragma unroll
        for (int i = 0; i < 4; ++i)
#pragma unroll
            for (int j = 0; j < 4; ++j) {
                float v = acc[i][j] + sB[32 + tx * 4 + j];
                sEA[(ey * 4 + i) * 33 + tx * 4 + j] = v > 0.f ? v : 0.f;
            }
    }
    __syncthreads();
    // layer 3: acc = EMB @ Wp1_c
    float acc[4][4];
#pragma unroll
    for (int i = 0; i < 4; ++i)
#pragma unroll
        for (int j = 0; j < 4; ++j) acc[i][j] = 0.f;
#pragma unroll
    for (int k = 0; k < 32; ++k) {
        float4 w = *(const float4*)&sW[2048 + k * 32 + tx * 4];
#pragma unroll
        for (int i = 0; i < 4; ++i) {
            float a = sEA[(ey * 4 + i) * 33 + k];
            acc[i][0] += a * w.x; acc[i][1] += a * w.y;
            acc[i][2] += a * w.z; acc[i][3] += a * w.w;
        }
    }

    // epilogue: pre = acc + P_a[row] + P_b[col] + bp1; out = relu(pre)@Wp2 + bp2
    float4 bp = *(const float4*)&bp1[tx * 4];
    float4 wp = *(const float4*)&Wp2[tx * 4];
    float bias2 = bp2[0];
#pragma unroll
    for (int i = 0; i < 4; ++i) {
        int e = ey * 4 + i;
        int r = sRow[e], c = sCol[e];
        float4 pa = *(const float4*)&g_p[(size_t)r * 64 + tx * 4];
        float4 pb = *(const float4*)&g_p[(size_t)c * 64 + 32 + tx * 4];
        float h0 = acc[i][0] + pa.x + pb.x + bp.x; h0 = h0 > 0.f ? h0 : 0.f;
        float h1 = acc[i][1] + pa.y + pb.y + bp.y; h1 = h1 > 0.f ? h1 : 0.f;
        float h2 = acc[i][2] + pa.z + pb.z + bp.z; h2 = h2 > 0.f ? h2 : 0.f;
        float h3 = acc[i][3] + pa.w + pb.w + bp.w; h3 = h3 > 0.f ? h3 : 0.f;
        float p = h0 * wp.x + h1 * wp.y + h2 * wp.z + h3 * wp.w;
        p += __shfl_down_sync(0xffffffffu, p, 4, 8);
        p += __shfl_down_sync(0xffffffffu, p, 2, 8);
        p += __shfl_down_sync(0xffffffffu, p, 1, 8);
        if (tx == 0) out[e0 + e] = p + bias2;
    }
}

// ---------------- host ----------------
extern "C" void kernel_launch(void* const* d_in, const int* in_sizes, int n_in,
                              void* d_out, int out_size)
{
    const float* x   = (const float*)d_in[0];
    const int*   ei  = (const int*)d_in[1];
    const float* ea  = (const float*)d_in[2];
    const float* W1  = (const float*)d_in[3];
    const float* as1 = (const float*)d_in[4];
    const float* ad1 = (const float*)d_in[5];
    const float* b1  = (const float*)d_in[6];
    const float* W2  = (const float*)d_in[7];
    const float* as2 = (const float*)d_in[8];
    const float* ad2 = (const float*)d_in[9];
    const float* b2  = (const float*)d_in[10];
    const float* Wm1 = (const float*)d_in[11];
    const float* bm1 = (const float*)d_in[12];
    const float* Wm2 = (const float*)d_in[13];
    const float* bm2 = (const float*)d_in[14];
    const float* Wp1 = (const float*)d_in[15];
    const float* bp1 = (const float*)d_in[16];
    const float* Wp2 = (const float*)d_in[17];
    const float* bp2 = (const float*)d_in[18];
    float* out = (float*)d_out;

    float *ph = nullptr, *px = nullptr, *pw = nullptr, *pp = nullptr;
    cudaGetSymbolAddress((void**)&ph, g_h);
    cudaGetSymbolAddress((void**)&px, g_x);
    cudaGetSymbolAddress((void**)&pw, g_wcat);
    cudaGetSymbolAddress((void**)&pp, g_p);

    const int EB  = (N_EDGES + 255) / 256;
    const int NB  = (N_NODES + 255) / 256;
    const int NWB = (N_NODES + 7) / 8;

    // ---- CSR build (once; reused by both layers) ----
    zero_cnt_kernel<<<NB, 256>>>();
    count_kernel<<<EB, 256>>>(ei);
    scan1_kernel<<<NB, 256>>>();
    scan2_kernel<<<1, 256>>>(NB);
    scan3_kernel<<<NB, 256>>>();
    scatter_kernel<<<EB, 256>>>(ei);

    for (int layer = 0; layer < 2; ++layer) {
        const float* X   = layer ? px : x;
        const int    K   = layer ? 256 : 128;
        const float* W   = layer ? W2 : W1;
        const float* as_ = layer ? as2 : as1;
        const float* ad_ = layer ? ad2 : ad1;
        const float* b_  = layer ? b2 : b1;

        tc_gemm_kernel<<<dim3(391, 4), 256>>>(X, W, ph, N_NODES, K, 256, 256, as_, ad_);
        gat_gather_kernel<<<NWB, 256>>>(b_);
    }
    pack_wcat_kernel<<<64, 256>>>(Wp1);
    tc_gemm_kernel<<<dim3(391, 1), 256>>>(px, pw, pp, N_NODES, 256, 64, 64,
                                          nullptr, nullptr);
    edge_pred_kernel<<<N_EDGES / 64, 128>>>(ei, ea,
                                            Wm1, bm1, Wm2, bm2,
                                            Wp1, bp1, Wp2, bp2, out);
}

// round 12
// speedup vs baseline: 1.1646x; 1.1417x over previous
#include <cuda_runtime.h>
#include <cuda_bf16.h>
#include <math.h>

#define N_NODES 50000
#define N_EDGES 400000
#define HEADS 8
#define HID 32
#define F 256            // HEADS*HID
#define NEG 0.2f

// ---------------- scratch (device globals: allocation-free) ----------------
__device__ float g_h[N_NODES * F];        // X @ W (pre-attention features)
__device__ float g_x[N_NODES * F];        // layer output
__device__ float g_asrc[N_NODES * HEADS];
__device__ float g_adst[N_NODES * HEADS];
__device__ float g_p[N_NODES * 64];       // [P_a | P_b] node projections
__device__ float g_wcat[256 * 64];        // [Wp1_a | Wp1_b] packed
__device__ int   g_cnt[N_NODES];
__device__ int   g_off[N_NODES + 1];
__device__ int   g_fill[N_NODES];
__device__ int   g_bsum[256];
__device__ int   g_csrc[N_EDGES];

__device__ __forceinline__ float leaky(float x) { return x > 0.f ? x : NEG * x; }

// pack two floats to bf16x2 (x in low half = first k element)
__device__ __forceinline__ unsigned pk(float x, float y) {
    __nv_bfloat162 h = __floats2bfloat162_rn(x, y);
    return *(unsigned*)&h;
}
__device__ __forceinline__ void split2(float x, float y, unsigned& hi, unsigned& lo) {
    float hx = __bfloat162float(__float2bfloat16_rn(x));
    float hy = __bfloat162float(__float2bfloat16_rn(y));
    hi = pk(hx, hy);
    lo = pk(x - hx, y - hy);
}

__device__ __forceinline__ void mma16(float* c,
    unsigned a0, unsigned a1, unsigned a2, unsigned a3,
    unsigned b0, unsigned b1)
{
    asm volatile(
        "mma.sync.aligned.m16n8k16.row.col.f32.bf16.bf16.f32 "
        "{%0,%1,%2,%3}, {%4,%5,%6,%7}, {%8,%9}, {%0,%1,%2,%3};"
        : "+f"(c[0]), "+f"(c[1]), "+f"(c[2]), "+f"(c[3])
        : "r"(a0), "r"(a1), "r"(a2), "r"(a3), "r"(b0), "r"(b1));
}

// ------ 3x bf16 split GEMM: C[M x N] = A[M x K] @ B[K x N], tile 128x64 ----
// 256 threads = 8 warps (4 warp_m x 2 warp_n), warp tile 32x32, BK=16.
// a = hi + lo (bf16 each); C = Ah Bh + Al Bh + Ah Bl  (error ~2^-18: < 1e-4)
// Register prefetch: next tile's global loads issued before the MMA phase.
// Optional fused epilogue: per-row attention dots (2 heads per block tile).
__global__ __launch_bounds__(256) void tc_gemm_kernel(
    const float* __restrict__ A, const float* __restrict__ B,
    float* __restrict__ C, int M, int K, int ldb, int ldc,
    const float* __restrict__ a_src, const float* __restrict__ a_dst)
{
    // [k-pair][m or n] packed bf16x2 along k
    __shared__ unsigned Ah[8][132], Al[8][132];
    __shared__ unsigned Bh[8][68],  Bl[8][68];
    __shared__ float sAs[64], sAd[64];

    const int tid = threadIdx.x;
    const int lane = tid & 31;
    const int wid = tid >> 5;
    const int warp_m = wid >> 1;          // rows warp_m*32
    const int warp_n = wid & 1;           // cols warp_n*32
    const int tig = lane & 3;
    const int grp = lane >> 2;
    const int m0 = blockIdx.x * 128;
    const int n0 = blockIdx.y * 64;

    if (a_src != nullptr && tid < 64) {
        sAs[tid] = a_src[n0 + tid];
        sAd[tid] = a_dst[n0 + tid];
    }

    // A-load coords: two 128-row fragments, 4 consecutive k each
    const int am0 = tid >> 2;             // 0..63
    const int am1 = am0 + 64;             // 64..127
    const int akp = (tid & 3) * 2;        // k-pair base (covers k akp*2..akp*2+3)
    // B-load coords: n = tid&63, k-pair halves
    const int bn = tid & 63;
    const int bkh = tid >> 6;             // 0..3 -> kp {bkh, bkh+4}

    float acc[2][4][4];
#pragma unroll
    for (int mf = 0; mf < 2; ++mf)
#pragma unroll
        for (int nf = 0; nf < 4; ++nf)
#pragma unroll
            for (int j = 0; j < 4; ++j) acc[mf][nf][j] = 0.f;

    // ---- prologue: prefetch tile 0 into registers ----
    float4 va0 = make_float4(0.f, 0.f, 0.f, 0.f);
    float4 va1 = make_float4(0.f, 0.f, 0.f, 0.f);
    float pb0, pb1, pb2, pb3;
    if (m0 + am0 < M) va0 = *(const float4*)&A[(size_t)(m0 + am0) * K + akp * 2];
    if (m0 + am1 < M) va1 = *(const float4*)&A[(size_t)(m0 + am1) * K + akp * 2];
    pb0 = B[(size_t)(2 * bkh) * ldb + n0 + bn];
    pb1 = B[(size_t)(2 * bkh + 1) * ldb + n0 + bn];
    pb2 = B[(size_t)(2 * (bkh + 4)) * ldb + n0 + bn];
    pb3 = B[(size_t)(2 * (bkh + 4) + 1) * ldb + n0 + bn];

    for (int k0 = 0; k0 < K; k0 += 16) {
        // ---- split current registers into smem ----
        {
            unsigned h, l;
            split2(va0.x, va0.y, h, l); Ah[akp][am0] = h;     Al[akp][am0] = l;
            split2(va0.z, va0.w, h, l); Ah[akp + 1][am0] = h; Al[akp + 1][am0] = l;
            split2(va1.x, va1.y, h, l); Ah[akp][am1] = h;     Al[akp][am1] = l;
            split2(va1.z, va1.w, h, l); Ah[akp + 1][am1] = h; Al[akp + 1][am1] = l;
            split2(pb0, pb1, h, l); Bh[bkh][bn] = h;     Bl[bkh][bn] = l;
            split2(pb2, pb3, h, l); Bh[bkh + 4][bn] = h; Bl[bkh + 4][bn] = l;
        }
        __syncthreads();

        // ---- prefetch next tile into registers (overlapped with MMAs) ----
        if (k0 + 16 < K) {
            va0 = make_float4(0.f, 0.f, 0.f, 0.f);
            va1 = make_float4(0.f, 0.f, 0.f, 0.f);
            if (m0 + am0 < M) va0 = *(const float4*)&A[(size_t)(m0 + am0) * K + k0 + 16 + akp * 2];
            if (m0 + am1 < M) va1 = *(const float4*)&A[(size_t)(m0 + am1) * K + k0 + 16 + akp * 2];
            pb0 = B[(size_t)(k0 + 16 + 2 * bkh) * ldb + n0 + bn];
            pb1 = B[(size_t)(k0 + 16 + 2 * bkh + 1) * ldb + n0 + bn];
            pb2 = B[(size_t)(k0 + 16 + 2 * (bkh + 4)) * ldb + n0 + bn];
            pb3 = B[(size_t)(k0 + 16 + 2 * (bkh + 4) + 1) * ldb + n0 + bn];
        }

        // ---- fragments + 24 MMAs ----
        unsigned ah[2][4], al_[2][4];
#pragma unroll
        for (int mf = 0; mf < 2; ++mf) {
            int mb = warp_m * 32 + mf * 16 + grp;
            ah[mf][0] = Ah[tig][mb];      al_[mf][0] = Al[tig][mb];
            ah[mf][1] = Ah[tig][mb + 8];  al_[mf][1] = Al[tig][mb + 8];
            ah[mf][2] = Ah[tig + 4][mb];      al_[mf][2] = Al[tig + 4][mb];
            ah[mf][3] = Ah[tig + 4][mb + 8];  al_[mf][3] = Al[tig + 4][mb + 8];
        }
#pragma unroll
        for (int nf = 0; nf < 4; ++nf) {
            int n = warp_n * 32 + nf * 8 + grp;
            unsigned bh0 = Bh[tig][n], bh1 = Bh[tig + 4][n];
            unsigned bl0 = Bl[tig][n], bl1 = Bl[tig + 4][n];
#pragma unroll
            for (int mf = 0; mf < 2; ++mf) {
                mma16(acc[mf][nf], ah[mf][0], ah[mf][1], ah[mf][2], ah[mf][3], bh0, bh1);
                mma16(acc[mf][nf], al_[mf][0], al_[mf][1], al_[mf][2], al_[mf][3], bh0, bh1);
                mma16(acc[mf][nf], ah[mf][0], ah[mf][1], ah[mf][2], ah[mf][3], bl0, bl1);
            }
        }
        __syncthreads();
    }

    // ---- store C (fragment mapping verified in rounds 5/9) ----
#pragma unroll
    for (int mf = 0; mf < 2; ++mf) {
        int r0 = m0 + warp_m * 32 + mf * 16 + grp;
        int r1 = r0 + 8;
#pragma unroll
        for (int nf = 0; nf < 4; ++nf) {
            int c = n0 + warp_n * 32 + nf * 8 + tig * 2;
            if (r0 < M)
                *(float2*)&C[(size_t)r0 * ldc + c] = make_float2(acc[mf][nf][0], acc[mf][nf][1]);
            if (r1 < M)
                *(float2*)&C[(size_t)r1 * ldc + c] = make_float2(acc[mf][nf][2], acc[mf][nf][3]);
        }
    }

    // ---- fused attention dots: head = n0/32 + warp_n ----
    if (a_src != nullptr) {
        const int head = (n0 >> 5) + warp_n;
#pragma unroll
        for (int mf = 0; mf < 2; ++mf) {
            float ps0 = 0.f, pd0 = 0.f, ps1 = 0.f, pd1 = 0.f;
#pragma unroll
            for (int nf = 0; nf < 4; ++nf) {
                int cl = warp_n * 32 + nf * 8 + tig * 2;
                float w0s = sAs[cl], w1s = sAs[cl + 1];
                float w0d = sAd[cl], w1d = sAd[cl + 1];
                ps0 += acc[mf][nf][0] * w0s + acc[mf][nf][1] * w1s;
                pd0 += acc[mf][nf][0] * w0d + acc[mf][nf][1] * w1d;
                ps1 += acc[mf][nf][2] * w0s + acc[mf][nf][3] * w1s;
                pd1 += acc[mf][nf][2] * w0d + acc[mf][nf][3] * w1d;
            }
#pragma unroll
            for (int off = 1; off <= 2; off <<= 1) {
                ps0 += __shfl_xor_sync(0xffffffffu, ps0, off);
                pd0 += __shfl_xor_sync(0xffffffffu, pd0, off);
                ps1 += __shfl_xor_sync(0xffffffffu, ps1, off);
                pd1 += __shfl_xor_sync(0xffffffffu, pd1, off);
            }
            if (tig == 0) {
                int r0 = m0 + warp_m * 32 + mf * 16 + grp;
                int r1 = r0 + 8;
                if (r0 < M) { g_asrc[r0 * 8 + head] = ps0; g_adst[r0 * 8 + head] = pd0; }
                if (r1 < M) { g_asrc[r1 * 8 + head] = ps1; g_adst[r1 * 8 + head] = pd1; }
            }
        }
    }
}

// ---------------- CSR build ----------------
__global__ __launch_bounds__(256) void zero_cnt_kernel()
{
    int i = blockIdx.x * blockDim.x + threadIdx.x;
    if (i < N_NODES) g_cnt[i] = 0;
}
__global__ __launch_bounds__(256) void count_kernel(const int* __restrict__ ei)
{
    int e = blockIdx.x * blockDim.x + threadIdx.x;
    if (e < N_EDGES) atomicAdd(&g_cnt[ei[N_EDGES + e]], 1);
}
__global__ __launch_bounds__(256) void scan1_kernel()
{
    __shared__ int sh[256];
    int i = blockIdx.x * 256 + threadIdx.x;
    int v = (i < N_NODES) ? g_cnt[i] : 0;
    sh[threadIdx.x] = v;
    __syncthreads();
#pragma unroll
    for (int off = 1; off < 256; off <<= 1) {
        int t = 0;
        if (threadIdx.x >= off) t = sh[threadIdx.x - off];
        __syncthreads();
        if (threadIdx.x >= off) sh[threadIdx.x] += t;
        __syncthreads();
    }
    if (i < N_NODES) g_off[i + 1] = sh[threadIdx.x];
    if (threadIdx.x == 255) g_bsum[blockIdx.x] = sh[255];
    if (i == 0) g_off[0] = 0;
}
__global__ __launch_bounds__(256) void scan2_kernel(int nblocks)
{
    __shared__ int sh[256];
    int t = threadIdx.x;
    int v = (t < nblocks) ? g_bsum[t] : 0;
    sh[t] = v;
    __syncthreads();
#pragma unroll
    for (int off = 1; off < 256; off <<= 1) {
        int u = 0;
        if (t >= off) u = sh[t - off];
        __syncthreads();
        if (t >= off) sh[t] += u;
        __syncthreads();
    }
    if (t < nblocks) g_bsum[t] = sh[t] - v;    // exclusive
}
__global__ __launch_bounds__(256) void scan3_kernel()
{
    int i = blockIdx.x * 256 + threadIdx.x;
    if (i < N_NODES) {
        int v = g_off[i + 1] + g_bsum[blockIdx.x];
        g_off[i + 1] = v;
        if (i + 1 < N_NODES) g_fill[i + 1] = v;
        if (i == 0) g_fill[0] = 0;
    }
}
__global__ __launch_bounds__(256) void scatter_kernel(const int* __restrict__ ei)
{
    int e = blockIdx.x * blockDim.x + threadIdx.x;
    if (e >= N_EDGES) return;
    int s = ei[e], d = ei[N_EDGES + e];
    int pos = atomicAdd(&g_fill[d], 1);
    g_csrc[pos] = s;
}

// -------- gather attention: one warp per node, fused softmax+agg+relu ------
__global__ __launch_bounds__(256) void gat_gather_kernel(const float* __restrict__ b)
{
    const int warp = threadIdx.x >> 5, lane = threadIdx.x & 31;
    const int n = blockIdx.x * 8 + warp;
    if (n >= N_NODES) return;
    const unsigned FULL = 0xffffffffu;
    const int h0 = lane >> 3, h1 = 4 + (lane >> 3);

    float myasrc = 0.f, myadst = 0.f;
    if (lane < 8) {
        myasrc = g_asrc[n * 8 + lane];
        myadst = g_adst[n * 8 + lane];
    }
    float4 acc0 = make_float4(0.f, 0.f, 0.f, 0.f);
    float4 acc1 = make_float4(0.f, 0.f, 0.f, 0.f);
    float denom = 0.f;

    const int beg = g_off[n], end = g_off[n + 1];
    for (int i = beg; i < end; ++i) {
        int s = g_csrc[i];
        float w = 0.f;
        if (lane < 8) {
            w = expf(leaky(g_asrc[s * 8 + lane] + myadst));
            denom += w;
        }
        float al0 = __shfl_sync(FULL, w, h0);
        float al1 = __shfl_sync(FULL, w, h1);
        float4 v0 = *(const float4*)&g_h[(size_t)s * 256 + lane * 4];
        float4 v1 = *(const float4*)&g_h[(size_t)s * 256 + 128 + lane * 4];
        acc0.x += al0 * v0.x; acc0.y += al0 * v0.y;
        acc0.z += al0 * v0.z; acc0.w += al0 * v0.w;
        acc1.x += al1 * v1.x; acc1.y += al1 * v1.y;
        acc1.z += al1 * v1.z; acc1.w += al1 * v1.w;
    }
    // self loop
    {
        float w = 0.f;
        if (lane < 8) {
            w = expf(leaky(myasrc + myadst));
            denom += w;
        }
        float al0 = __shfl_sync(FULL, w, h0);
        float al1 = __shfl_sync(FULL, w, h1);
        float4 v0 = *(const float4*)&g_h[(size_t)n * 256 + lane * 4];
        float4 v1 = *(const float4*)&g_h[(size_t)n * 256 + 128 + lane * 4];
        acc0.x += al0 * v0.x; acc0.y += al0 * v0.y;
        acc0.z += al0 * v0.z; acc0.w += al0 * v0.w;
        acc1.x += al1 * v1.x; acc1.y += al1 * v1.y;
        acc1.z += al1 * v1.z; acc1.w += al1 * v1.w;
    }
    float inv0 = 1.f / __shfl_sync(FULL, denom, h0);
    float inv1 = 1.f / __shfl_sync(FULL, denom, h1);
    float4 bb0 = *(const float4*)&b[lane * 4];
    float4 bb1 = *(const float4*)&b[128 + lane * 4];
    float4 o0, o1;
    o0.x = fmaxf(acc0.x * inv0 + bb0.x, 0.f);
    o0.y = fmaxf(acc0.y * inv0 + bb0.y, 0.f);
    o0.z = fmaxf(acc0.z * inv0 + bb0.z, 0.f);
    o0.w = fmaxf(acc0.w * inv0 + bb0.w, 0.f);
    o1.x = fmaxf(acc1.x * inv1 + bb1.x, 0.f);
    o1.y = fmaxf(acc1.y * inv1 + bb1.y, 0.f);
    o1.z = fmaxf(acc1.z * inv1 + bb1.z, 0.f);
    o1.w = fmaxf(acc1.w * inv1 + bb1.w, 0.f);
    *(float4*)&g_x[(size_t)n * 256 + lane * 4] = o0;
    *(float4*)&g_x[(size_t)n * 256 + 128 + lane * 4] = o1;
}

// ---------------- pack Wcat = [Wp1_a | Wp1_b] : [256 x 64] ----------------
__global__ __launch_bounds__(256) void pack_wcat_kernel(const float* __restrict__ Wp1)
{
    int i = blockIdx.x * blockDim.x + threadIdx.x;
    if (i >= 256 * 64) return;
    int k = i >> 6, j = i & 63;
    g_wcat[i] = (j < 32) ? Wp1[k * 32 + j] : Wp1[(256 + k) * 32 + (j - 32)];
}

// ---------------- edge predictor: emb MLP + combine (fp32) ----------------
__global__ __launch_bounds__(128) void edge_pred_kernel(
    const int* __restrict__ ei, const float* __restrict__ edge_attr,
    const float* __restrict__ Wm1, const float* __restrict__ bm1,
    const float* __restrict__ Wm2, const float* __restrict__ bm2,
    const float* __restrict__ Wp1, const float* __restrict__ bp1,
    const float* __restrict__ Wp2, const float* __restrict__ bp2,
    float* __restrict__ out)
{
    __shared__ float sEA[64 * 33];
    __shared__ float sT1[64 * 33];
    __shared__ float sW[3072];          // Wm1 | Wm2 | Wp1_c
    __shared__ int   sRow[64], sCol[64];
    __shared__ float sB[64];            // bm1 | bm2

    const int tid = threadIdx.x;
    const int tx = tid & 7;
    const int ey = tid >> 3;
    const int e0 = blockIdx.x * 64;

    if (tid < 64) {
        sRow[tid] = ei[e0 + tid];
        sCol[tid] = ei[N_EDGES + e0 + tid];
    }
    for (int i = tid; i < 3072; i += 128)
        sW[i] = (i < 1024) ? Wm1[i]
              : (i < 2048) ? Wm2[i - 1024]
                           : Wp1[512 * 32 + (i - 2048)];
    if (tid < 32) { sB[tid] = bm1[tid]; sB[32 + tid] = bm2[tid]; }
    for (int f = tid; f < 64 * 8; f += 128) {
        int e = f >> 3, q = f & 7;
        float4 v = *(const float4*)&edge_attr[(size_t)(e0 + e) * 32 + q * 4];
        float* p = &sEA[e * 33 + q * 4];
        p[0] = v.x; p[1] = v.y; p[2] = v.z; p[3] = v.w;
    }
    __syncthreads();

    // layer 1: T1 = relu(EA @ Wm1 + bm1)
    {
        float acc[4][4];
#pragma unroll
        for (int i = 0; i < 4; ++i)
#pragma unroll
            for (int j = 0; j < 4; ++j) acc[i][j] = 0.f;
#pragma unroll
        for (int k = 0; k < 32; ++k) {
            float4 w = *(const float4*)&sW[k * 32 + tx * 4];
#pragma unroll
            for (int i = 0; i < 4; ++i) {
                float a = sEA[(ey * 4 + i) * 33 + k];
                acc[i][0] += a * w.x; acc[i][1] += a * w.y;
                acc[i][2] += a * w.z; acc[i][3] += a * w.w;
            }
        }
#pragma unroll
        for (int i = 0; i < 4; ++i)
#pragma unroll
            for (int j = 0; j < 4; ++j) {
                float v = acc[i][j] + sB[tx * 4 + j];
                sT1[(ey * 4 + i) * 33 + tx * 4 + j] = v > 0.f ? v : 0.f;
            }
    }
    __syncthreads();
    // layer 2: EMB = relu(T1 @ Wm2 + bm2) -> sEA (reuse)
    {
        float acc[4][4];
#pragma unroll
        for (int i = 0; i < 4; ++i)
#pragma unroll
            for (int j = 0; j < 4; ++j) acc[i][j] = 0.f;
#pragma unroll
        for (int k = 0; k < 32; ++k) {
            float4 w = *(const float4*)&sW[1024 + k * 32 + tx * 4];
#pragma unroll
            for (int i = 0; i < 4; ++i) {
                float a = sT1[(ey * 4 + i) * 33 + k];
                acc[i][0] += a * w.x; acc[i][1] += a * w.y;
                acc[i][2] += a * w.z; acc[i][3] += a * w.w;
            }
        }
        __syncthreads();
#pragma unroll
        for (int i = 0; i < 4; ++i)
#pragma unroll
            for (int j = 0; j < 4; ++j) {
                float v = acc[i][j] + sB[32 + tx * 4 + j];
                sEA[(ey * 4 + i) * 33 + tx * 4 + j] = v > 0.f ? v : 0.f;
            }
    }
    __syncthreads();
    // layer 3: acc = EMB @ Wp1_c
    float acc[4][4];
#pragma unroll
    for (int i = 0; i < 4; ++i)
#pragma unroll
        for (int j = 0; j < 4; ++j) acc[i][j] = 0.f;
#pragma unroll
    for (int k = 0; k < 32; ++k) {
        float4 w = *(const float4*)&sW[2048 + k * 32 + tx * 4];
#pragma unroll
        for (int i = 0; i < 4; ++i) {
            float a = sEA[(ey * 4 + i) * 33 + k];
            acc[i][0] += a * w.x; acc[i][1] += a * w.y;
            acc[i][2] += a * w.z; acc[i][3] += a * w.w;
        }
    }

    // epilogue: pre = acc + P_a[row] + P_b[col] + bp1; out = relu(pre)@Wp2 + bp2
    float4 bp = *(const float4*)&bp1[tx * 4];
    float4 wp = *(const float4*)&Wp2[tx * 4];
    float bias2 = bp2[0];
#pragma unroll
    for (int i = 0; i < 4; ++i) {
        int e = ey * 4 + i;
        int r = sRow[e], c = sCol[e];
        float4 pa = *(const float4*)&g_p[(size_t)r * 64 + tx * 4];
        float4 pb = *(const float4*)&g_p[(size_t)c * 64 + 32 + tx * 4];
        float h0 = acc[i][0] + pa.x + pb.x + bp.x; h0 = h0 > 0.f ? h0 : 0.f;
        float h1 = acc[i][1] + pa.y + pb.y + bp.y; h1 = h1 > 0.f ? h1 : 0.f;
        float h2 = acc[i][2] + pa.z + pb.z + bp.z; h2 = h2 > 0.f ? h2 : 0.f;
        float h3 = acc[i][3] + pa.w + pb.w + bp.w; h3 = h3 > 0.f ? h3 : 0.f;
        float p = h0 * wp.x + h1 * wp.y + h2 * wp.z + h3 * wp.w;
        p += __shfl_down_sync(0xffffffffu, p, 4, 8);
        p += __shfl_down_sync(0xffffffffu, p, 2, 8);
        p += __shfl_down_sync(0xffffffffu, p, 1, 8);
        if (tx == 0) out[e0 + e] = p + bias2;
    }
}

// ---------------- host ----------------
extern "C" void kernel_launch(void* const* d_in, const int* in_sizes, int n_in,
                              void* d_out, int out_size)
{
    const float* x   = (const float*)d_in[0];
    const int*   ei  = (const int*)d_in[1];
    const float* ea  = (const float*)d_in[2];
    const float* W1  = (const float*)d_in[3];
    const float* as1 = (const float*)d_in[4];
    const float* ad1 = (const float*)d_in[5];
    const float* b1  = (const float*)d_in[6];
    const float* W2  = (const float*)d_in[7];
    const float* as2 = (const float*)d_in[8];
    const float* ad2 = (const float*)d_in[9];
    const float* b2  = (const float*)d_in[10];
    const float* Wm1 = (const float*)d_in[11];
    const float* bm1 = (const float*)d_in[12];
    const float* Wm2 = (const float*)d_in[13];
    const float* bm2 = (const float*)d_in[14];
    const float* Wp1 = (const float*)d_in[15];
    const float* bp1 = (const float*)d_in[16];
    const float* Wp2 = (const float*)d_in[17];
    const float* bp2 = (const float*)d_in[18];
    float* out = (float*)d_out;

    float *ph = nullptr, *px = nullptr, *pw = nullptr, *pp = nullptr;
    cudaGetSymbolAddress((void**)&ph, g_h);
    cudaGetSymbolAddress((void**)&px, g_x);
    cudaGetSymbolAddress((void**)&pw, g_wcat);
    cudaGetSymbolAddress((void**)&pp, g_p);

    const int EB  = (N_EDGES + 255) / 256;
    const int NB  = (N_NODES + 255) / 256;
    const int NWB = (N_NODES + 7) / 8;

    // ---- CSR build (once; reused by both layers) ----
    zero_cnt_kernel<<<NB, 256>>>();
    count_kernel<<<EB, 256>>>(ei);
    scan1_kernel<<<NB, 256>>>();
    scan2_kernel<<<1, 256>>>(NB);
    scan3_kernel<<<NB, 256>>>();
    scatter_kernel<<<EB, 256>>>(ei);

    for (int layer = 0; layer < 2; ++layer) {
        const float* X   = layer ? px : x;
        const int    K   = layer ? 256 : 128;
        const float* W   = layer ? W2 : W1;
        const float* as_ = layer ? as2 : as1;
        const float* ad_ = layer ? ad2 : ad1;
        const float* b_  = layer ? b2 : b1;

        tc_gemm_kernel<<<dim3(391, 4), 256>>>(X, W, ph, N_NODES, K, 256, 256, as_, ad_);
        gat_gather_kernel<<<NWB, 256>>>(b_);
    }
    pack_wcat_kernel<<<64, 256>>>(Wp1);
    tc_gemm_kernel<<<dim3(391, 1), 256>>>(px, pw, pp, N_NODES, 256, 64, 64,
                                          nullptr, nullptr);
    edge_pred_kernel<<<N_EDGES / 64, 128>>>(ei, ea,
                                            Wm1, bm1, Wm2, bm2,
                                            Wp1, bp1, Wp2, bp2, out);
}

// round 13
// speedup vs baseline: 1.1942x; 1.0254x over previous
#include <cuda_runtime.h>
#include <cuda_bf16.h>
#include <math.h>

#define N_NODES 50000
#define N_EDGES 400000
#define HEADS 8
#define HID 32
#define F 256            // HEADS*HID
#define NEG 0.2f

// ---------------- scratch (device globals: allocation-free) ----------------
__device__ float g_h[N_NODES * F];        // X @ W (pre-attention features)
__device__ float g_x[N_NODES * F];        // layer output
__device__ float g_asrc[N_NODES * HEADS];
__device__ float g_adst[N_NODES * HEADS];
__device__ float g_p[N_NODES * 64];       // [P_a | P_b] node projections
__device__ float g_wcat[256 * 64];        // [Wp1_a | Wp1_b] packed
__device__ int   g_cnt[N_NODES];
__device__ int   g_off[N_NODES + 1];
__device__ int   g_fill[N_NODES];
__device__ int   g_bsum[256];
__device__ int   g_csrc[N_EDGES];

__device__ __forceinline__ float leaky(float x) { return x > 0.f ? x : NEG * x; }

// pack two floats to bf16x2 (x in low half = first k element)
__device__ __forceinline__ unsigned pk(float x, float y) {
    __nv_bfloat162 h = __floats2bfloat162_rn(x, y);
    return *(unsigned*)&h;
}
__device__ __forceinline__ void split2(float x, float y, unsigned& hi, unsigned& lo) {
    float hx = __bfloat162float(__float2bfloat16_rn(x));
    float hy = __bfloat162float(__float2bfloat16_rn(y));
    hi = pk(hx, hy);
    lo = pk(x - hx, y - hy);
}

__device__ __forceinline__ void mma16(float* c,
    unsigned a0, unsigned a1, unsigned a2, unsigned a3,
    unsigned b0, unsigned b1)
{
    asm volatile(
        "mma.sync.aligned.m16n8k16.row.col.f32.bf16.bf16.f32 "
        "{%0,%1,%2,%3}, {%4,%5,%6,%7}, {%8,%9}, {%0,%1,%2,%3};"
        : "+f"(c[0]), "+f"(c[1]), "+f"(c[2]), "+f"(c[3])
        : "r"(a0), "r"(a1), "r"(a2), "r"(a3), "r"(b0), "r"(b1));
}

// ------ 3x bf16 split GEMM: C[M x N] = A[M x K] @ B[K x N], tile 128x64 ----
// (round-12 version: register prefetch + fused attention-dot epilogue)
__global__ __launch_bounds__(256) void tc_gemm_kernel(
    const float* __restrict__ A, const float* __restrict__ B,
    float* __restrict__ C, int M, int K, int ldb, int ldc,
    const float* __restrict__ a_src, const float* __restrict__ a_dst)
{
    __shared__ unsigned Ah[8][132], Al[8][132];
    __shared__ unsigned Bh[8][68],  Bl[8][68];
    __shared__ float sAs[64], sAd[64];

    const int tid = threadIdx.x;
    const int lane = tid & 31;
    const int wid = tid >> 5;
    const int warp_m = wid >> 1;
    const int warp_n = wid & 1;
    const int tig = lane & 3;
    const int grp = lane >> 2;
    const int m0 = blockIdx.x * 128;
    const int n0 = blockIdx.y * 64;

    if (a_src != nullptr && tid < 64) {
        sAs[tid] = a_src[n0 + tid];
        sAd[tid] = a_dst[n0 + tid];
    }

    const int am0 = tid >> 2;
    const int am1 = am0 + 64;
    const int akp = (tid & 3) * 2;
    const int bn = tid & 63;
    const int bkh = tid >> 6;

    float acc[2][4][4];
#pragma unroll
    for (int mf = 0; mf < 2; ++mf)
#pragma unroll
        for (int nf = 0; nf < 4; ++nf)
#pragma unroll
            for (int j = 0; j < 4; ++j) acc[mf][nf][j] = 0.f;

    float4 va0 = make_float4(0.f, 0.f, 0.f, 0.f);
    float4 va1 = make_float4(0.f, 0.f, 0.f, 0.f);
    float pb0, pb1, pb2, pb3;
    if (m0 + am0 < M) va0 = *(const float4*)&A[(size_t)(m0 + am0) * K + akp * 2];
    if (m0 + am1 < M) va1 = *(const float4*)&A[(size_t)(m0 + am1) * K + akp * 2];
    pb0 = B[(size_t)(2 * bkh) * ldb + n0 + bn];
    pb1 = B[(size_t)(2 * bkh + 1) * ldb + n0 + bn];
    pb2 = B[(size_t)(2 * (bkh + 4)) * ldb + n0 + bn];
    pb3 = B[(size_t)(2 * (bkh + 4) + 1) * ldb + n0 + bn];

    for (int k0 = 0; k0 < K; k0 += 16) {
        {
            unsigned h, l;
            split2(va0.x, va0.y, h, l); Ah[akp][am0] = h;     Al[akp][am0] = l;
            split2(va0.z, va0.w, h, l); Ah[akp + 1][am0] = h; Al[akp + 1][am0] = l;
            split2(va1.x, va1.y, h, l); Ah[akp][am1] = h;     Al[akp][am1] = l;
            split2(va1.z, va1.w, h, l); Ah[akp + 1][am1] = h; Al[akp + 1][am1] = l;
            split2(pb0, pb1, h, l); Bh[bkh][bn] = h;     Bl[bkh][bn] = l;
            split2(pb2, pb3, h, l); Bh[bkh + 4][bn] = h; Bl[bkh + 4][bn] = l;
        }
        __syncthreads();

        if (k0 + 16 < K) {
            va0 = make_float4(0.f, 0.f, 0.f, 0.f);
            va1 = make_float4(0.f, 0.f, 0.f, 0.f);
            if (m0 + am0 < M) va0 = *(const float4*)&A[(size_t)(m0 + am0) * K + k0 + 16 + akp * 2];
            if (m0 + am1 < M) va1 = *(const float4*)&A[(size_t)(m0 + am1) * K + k0 + 16 + akp * 2];
            pb0 = B[(size_t)(k0 + 16 + 2 * bkh) * ldb + n0 + bn];
            pb1 = B[(size_t)(k0 + 16 + 2 * bkh + 1) * ldb + n0 + bn];
            pb2 = B[(size_t)(k0 + 16 + 2 * (bkh + 4)) * ldb + n0 + bn];
            pb3 = B[(size_t)(k0 + 16 + 2 * (bkh + 4) + 1) * ldb + n0 + bn];
        }

        unsigned ah[2][4], al_[2][4];
#pragma unroll
        for (int mf = 0; mf < 2; ++mf) {
            int mb = warp_m * 32 + mf * 16 + grp;
            ah[mf][0] = Ah[tig][mb];      al_[mf][0] = Al[tig][mb];
            ah[mf][1] = Ah[tig][mb + 8];  al_[mf][1] = Al[tig][mb + 8];
            ah[mf][2] = Ah[tig + 4][mb];      al_[mf][2] = Al[tig + 4][mb];
            ah[mf][3] = Ah[tig + 4][mb + 8];  al_[mf][3] = Al[tig + 4][mb + 8];
        }
#pragma unroll
        for (int nf = 0; nf < 4; ++nf) {
            int n = warp_n * 32 + nf * 8 + grp;
            unsigned bh0 = Bh[tig][n], bh1 = Bh[tig + 4][n];
            unsigned bl0 = Bl[tig][n], bl1 = Bl[tig + 4][n];
#pragma unroll
            for (int mf = 0; mf < 2; ++mf) {
                mma16(acc[mf][nf], ah[mf][0], ah[mf][1], ah[mf][2], ah[mf][3], bh0, bh1);
                mma16(acc[mf][nf], al_[mf][0], al_[mf][1], al_[mf][2], al_[mf][3], bh0, bh1);
                mma16(acc[mf][nf], ah[mf][0], ah[mf][1], ah[mf][2], ah[mf][3], bl0, bl1);
            }
        }
        __syncthreads();
    }

#pragma unroll
    for (int mf = 0; mf < 2; ++mf) {
        int r0 = m0 + warp_m * 32 + mf * 16 + grp;
        int r1 = r0 + 8;
#pragma unroll
        for (int nf = 0; nf < 4; ++nf) {
            int c = n0 + warp_n * 32 + nf * 8 + tig * 2;
            if (r0 < M)
                *(float2*)&C[(size_t)r0 * ldc + c] = make_float2(acc[mf][nf][0], acc[mf][nf][1]);
            if (r1 < M)
                *(float2*)&C[(size_t)r1 * ldc + c] = make_float2(acc[mf][nf][2], acc[mf][nf][3]);
        }
    }

    if (a_src != nullptr) {
        const int head = (n0 >> 5) + warp_n;
#pragma unroll
        for (int mf = 0; mf < 2; ++mf) {
            float ps0 = 0.f, pd0 = 0.f, ps1 = 0.f, pd1 = 0.f;
#pragma unroll
            for (int nf = 0; nf < 4; ++nf) {
                int cl = warp_n * 32 + nf * 8 + tig * 2;
                float w0s = sAs[cl], w1s = sAs[cl + 1];
                float w0d = sAd[cl], w1d = sAd[cl + 1];
                ps0 += acc[mf][nf][0] * w0s + acc[mf][nf][1] * w1s;
                pd0 += acc[mf][nf][0] * w0d + acc[mf][nf][1] * w1d;
                ps1 += acc[mf][nf][2] * w0s + acc[mf][nf][3] * w1s;
                pd1 += acc[mf][nf][2] * w0d + acc[mf][nf][3] * w1d;
            }
#pragma unroll
            for (int off = 1; off <= 2; off <<= 1) {
                ps0 += __shfl_xor_sync(0xffffffffu, ps0, off);
                pd0 += __shfl_xor_sync(0xffffffffu, pd0, off);
                ps1 += __shfl_xor_sync(0xffffffffu, ps1, off);
                pd1 += __shfl_xor_sync(0xffffffffu, pd1, off);
            }
            if (tig == 0) {
                int r0 = m0 + warp_m * 32 + mf * 16 + grp;
                int r1 = r0 + 8;
                if (r0 < M) { g_asrc[r0 * 8 + head] = ps0; g_adst[r0 * 8 + head] = pd0; }
                if (r1 < M) { g_asrc[r1 * 8 + head] = ps1; g_adst[r1 * 8 + head] = pd1; }
            }
        }
    }
}

// ---------------- CSR build ----------------
__global__ __launch_bounds__(256) void zero_cnt_kernel()
{
    int i = blockIdx.x * blockDim.x + threadIdx.x;
    if (i < N_NODES) g_cnt[i] = 0;
}
__global__ __launch_bounds__(256) void count_kernel(const int* __restrict__ ei)
{
    int e = blockIdx.x * blockDim.x + threadIdx.x;
    if (e < N_EDGES) atomicAdd(&g_cnt[ei[N_EDGES + e]], 1);
}
__global__ __launch_bounds__(256) void scan1_kernel()
{
    __shared__ int sh[256];
    int i = blockIdx.x * 256 + threadIdx.x;
    int v = (i < N_NODES) ? g_cnt[i] : 0;
    sh[threadIdx.x] = v;
    __syncthreads();
#pragma unroll
    for (int off = 1; off < 256; off <<= 1) {
        int t = 0;
        if (threadIdx.x >= off) t = sh[threadIdx.x - off];
        __syncthreads();
        if (threadIdx.x >= off) sh[threadIdx.x] += t;
        __syncthreads();
    }
    if (i < N_NODES) g_off[i + 1] = sh[threadIdx.x];
    if (threadIdx.x == 255) g_bsum[blockIdx.x] = sh[255];
    if (i == 0) g_off[0] = 0;
}
__global__ __launch_bounds__(256) void scan2_kernel(int nblocks)
{
    __shared__ int sh[256];
    int t = threadIdx.x;
    int v = (t < nblocks) ? g_bsum[t] : 0;
    sh[t] = v;
    __syncthreads();
#pragma unroll
    for (int off = 1; off < 256; off <<= 1) {
        int u = 0;
        if (t >= off) u = sh[t - off];
        __syncthreads();
        if (t >= off) sh[t] += u;
        __syncthreads();
    }
    if (t < nblocks) g_bsum[t] = sh[t] - v;    // exclusive
}
__global__ __launch_bounds__(256) void scan3_kernel()
{
    int i = blockIdx.x * 256 + threadIdx.x;
    if (i < N_NODES) {
        int v = g_off[i + 1] + g_bsum[blockIdx.x];
        g_off[i + 1] = v;
        if (i + 1 < N_NODES) g_fill[i + 1] = v;
        if (i == 0) g_fill[0] = 0;
    }
}
__global__ __launch_bounds__(256) void scatter_kernel(const int* __restrict__ ei)
{
    int e = blockIdx.x * blockDim.x + threadIdx.x;
    if (e >= N_EDGES) return;
    int s = ei[e], d = ei[N_EDGES + e];
    int pos = atomicAdd(&g_fill[d], 1);
    g_csrc[pos] = s;
}

// -------- gather attention: one warp per node, fused softmax+agg+relu ------
__global__ __launch_bounds__(256) void gat_gather_kernel(const float* __restrict__ b)
{
    const int warp = threadIdx.x >> 5, lane = threadIdx.x & 31;
    const int n = blockIdx.x * 8 + warp;
    if (n >= N_NODES) return;
    const unsigned FULL = 0xffffffffu;
    const int h0 = lane >> 3, h1 = 4 + (lane >> 3);

    float myasrc = 0.f, myadst = 0.f;
    if (lane < 8) {
        myasrc = g_asrc[n * 8 + lane];
        myadst = g_adst[n * 8 + lane];
    }
    float4 acc0 = make_float4(0.f, 0.f, 0.f, 0.f);
    float4 acc1 = make_float4(0.f, 0.f, 0.f, 0.f);
    float denom = 0.f;

    const int beg = g_off[n], end = g_off[n + 1];
    for (int i = beg; i < end; ++i) {
        int s = g_csrc[i];
        float w = 0.f;
        if (lane < 8) {
            w = expf(leaky(g_asrc[s * 8 + lane] + myadst));
            denom += w;
        }
        float al0 = __shfl_sync(FULL, w, h0);
        float al1 = __shfl_sync(FULL, w, h1);
        float4 v0 = *(const float4*)&g_h[(size_t)s * 256 + lane * 4];
        float4 v1 = *(const float4*)&g_h[(size_t)s * 256 + 128 + lane * 4];
        acc0.x += al0 * v0.x; acc0.y += al0 * v0.y;
        acc0.z += al0 * v0.z; acc0.w += al0 * v0.w;
        acc1.x += al1 * v1.x; acc1.y += al1 * v1.y;
        acc1.z += al1 * v1.z; acc1.w += al1 * v1.w;
    }
    // self loop
    {
        float w = 0.f;
        if (lane < 8) {
            w = expf(leaky(myasrc + myadst));
            denom += w;
        }
        float al0 = __shfl_sync(FULL, w, h0);
        float al1 = __shfl_sync(FULL, w, h1);
        float4 v0 = *(const float4*)&g_h[(size_t)n * 256 + lane * 4];
        float4 v1 = *(const float4*)&g_h[(size_t)n * 256 + 128 + lane * 4];
        acc0.x += al0 * v0.x; acc0.y += al0 * v0.y;
        acc0.z += al0 * v0.z; acc0.w += al0 * v0.w;
        acc1.x += al1 * v1.x; acc1.y += al1 * v1.y;
        acc1.z += al1 * v1.z; acc1.w += al1 * v1.w;
    }
    float inv0 = 1.f / __shfl_sync(FULL, denom, h0);
    float inv1 = 1.f / __shfl_sync(FULL, denom, h1);
    float4 bb0 = *(const float4*)&b[lane * 4];
    float4 bb1 = *(const float4*)&b[128 + lane * 4];
    float4 o0, o1;
    o0.x = fmaxf(acc0.x * inv0 + bb0.x, 0.f);
    o0.y = fmaxf(acc0.y * inv0 + bb0.y, 0.f);
    o0.z = fmaxf(acc0.z * inv0 + bb0.z, 0.f);
    o0.w = fmaxf(acc0.w * inv0 + bb0.w, 0.f);
    o1.x = fmaxf(acc1.x * inv1 + bb1.x, 0.f);
    o1.y = fmaxf(acc1.y * inv1 + bb1.y, 0.f);
    o1.z = fmaxf(acc1.z * inv1 + bb1.z, 0.f);
    o1.w = fmaxf(acc1.w * inv1 + bb1.w, 0.f);
    *(float4*)&g_x[(size_t)n * 256 + lane * 4] = o0;
    *(float4*)&g_x[(size_t)n * 256 + 128 + lane * 4] = o1;
}

// ---------------- pack Wcat = [Wp1_a | Wp1_b] : [256 x 64] ----------------
__global__ __launch_bounds__(256) void pack_wcat_kernel(const float* __restrict__ Wp1)
{
    int i = blockIdx.x * blockDim.x + threadIdx.x;
    if (i >= 256 * 64) return;
    int k = i >> 6, j = i & 63;
    g_wcat[i] = (j < 32) ? Wp1[k * 32 + j] : Wp1[(256 + k) * 32 + (j - 32)];
}

// ------- edge predictor: bf16-split tensor-core edge-MLP + exact combine ---
// 64 edges/block (M=64), 128 threads = 4 warps, warp tile m16 n32 k32.
// Layer I/O lives in [k-pair][m] smem buffers (same convention as tc_gemm);
// the m16n8k16 output fragment (cols 2tig,2tig+1) IS a k-pair, so bias+relu+
// split2 stores straight into the next layer's input layout. Rows are
// warp-private -> only __syncwarp between layers.
__global__ __launch_bounds__(128) void edge_pred_kernel(
    const int* __restrict__ ei, const float* __restrict__ edge_attr,
    const float* __restrict__ Wm1, const float* __restrict__ bm1,
    const float* __restrict__ Wm2, const float* __restrict__ bm2,
    const float* __restrict__ Wp1, const float* __restrict__ bp1,
    const float* __restrict__ Wp2, const float* __restrict__ bp2,
    float* __restrict__ out)
{
    __shared__ unsigned XH[16][66], XL[16][66];    // ping buffer
    __shared__ unsigned YH[16][66], YL[16][66];    // pong buffer
    __shared__ unsigned W1h[16][33], W1l[16][33];
    __shared__ unsigned W2h[16][33], W2l[16][33];
    __shared__ unsigned W3h[16][33], W3l[16][33];
    __shared__ int   sRow[64], sCol[64];
    __shared__ float sB[64];                       // bm1 | bm2

    const int tid = threadIdx.x;
    const int lane = tid & 31;
    const int wrp = tid >> 5;
    const int tig = lane & 3;
    const int grp = lane >> 2;
    const int e0 = blockIdx.x * 64;
    const int m0l = wrp * 16 + grp;                // local edge row (0..63)

    if (tid < 64) {
        sRow[tid] = ei[e0 + tid];
        sCol[tid] = ei[N_EDGES + e0 + tid];
    }
    if (tid < 32) { sB[tid] = bm1[tid]; sB[32 + tid] = bm2[tid]; }

    // pack the three 32x32 weights into [kp][n] bf16x2 hi/lo
    for (int i = tid; i < 512; i += 128) {
        int kp = i >> 5, n = i & 31;
        unsigned h, l;
        split2(Wm1[(2 * kp) * 32 + n], Wm1[(2 * kp + 1) * 32 + n], h, l);
        W1h[kp][n] = h; W1l[kp][n] = l;
        split2(Wm2[(2 * kp) * 32 + n], Wm2[(2 * kp + 1) * 32 + n], h, l);
        W2h[kp][n] = h; W2l[kp][n] = l;
        split2(Wp1[(512 + 2 * kp) * 32 + n], Wp1[(512 + 2 * kp + 1) * 32 + n], h, l);
        W3h[kp][n] = h; W3l[kp][n] = l;
    }
    // load EA split into X
    for (int f = tid; f < 512; f += 128) {
        int e = f >> 3, q = f & 7;
        float4 v = *(const float4*)&edge_attr[(size_t)(e0 + e) * 32 + q * 4];
        unsigned h, l;
        split2(v.x, v.y, h, l); XH[2 * q][e] = h;     XL[2 * q][e] = l;
        split2(v.z, v.w, h, l); XH[2 * q + 1][e] = h; XL[2 * q + 1][e] = l;
    }
    __syncthreads();

    float acc[4][4];

    // ---- macro-free layer compute: acc = I @ W (3-pass bf16 split) ----
#define EP_COMPUTE(IH, IL, WH, WL)                                            \
    {                                                                         \
        _Pragma("unroll")                                                     \
        for (int nf = 0; nf < 4; ++nf)                                        \
            _Pragma("unroll")                                                 \
            for (int j = 0; j < 4; ++j) acc[nf][j] = 0.f;                     \
        _Pragma("unroll")                                                     \
        for (int ks = 0; ks < 2; ++ks) {                                      \
            int kb = ks * 8;                                                  \
            unsigned a0 = IH[kb + tig][m0l],     l0 = IL[kb + tig][m0l];      \
            unsigned a1 = IH[kb + tig][m0l + 8], l1 = IL[kb + tig][m0l + 8];  \
            unsigned a2 = IH[kb + tig + 4][m0l],     l2 = IL[kb + tig + 4][m0l];     \
            unsigned a3 = IH[kb + tig + 4][m0l + 8], l3 = IL[kb + tig + 4][m0l + 8]; \
            _Pragma("unroll")                                                 \
            for (int nf = 0; nf < 4; ++nf) {                                  \
                int n = nf * 8 + grp;                                         \
                unsigned bh0 = WH[kb + tig][n], bh1 = WH[kb + tig + 4][n];    \
                unsigned bl0 = WL[kb + tig][n], bl1 = WL[kb + tig + 4][n];    \
                mma16(acc[nf], a0, a1, a2, a3, bh0, bh1);                     \
                mma16(acc[nf], l0, l1, l2, l3, bh0, bh1);                     \
                mma16(acc[nf], a0, a1, a2, a3, bl0, bl1);                     \
            }                                                                 \
        }                                                                     \
    }
    // ---- bias+relu+split -> output buffer (fragment cols form k-pairs) ----
#define EP_STORE(OH, OL, boff)                                                \
    {                                                                         \
        _Pragma("unroll")                                                     \
        for (int nf = 0; nf < 4; ++nf) {                                      \
            int j0 = nf * 8 + 2 * tig;                                        \
            int kp = nf * 4 + tig;                                            \
            float b0 = sB[boff + j0], b1 = sB[boff + j0 + 1];                 \
            float v0 = fmaxf(acc[nf][0] + b0, 0.f);                           \
            float v1 = fmaxf(acc[nf][1] + b1, 0.f);                           \
            float v2 = fmaxf(acc[nf][2] + b0, 0.f);                           \
            float v3 = fmaxf(acc[nf][3] + b1, 0.f);                           \
            unsigned h, l;                                                    \
            split2(v0, v1, h, l); OH[kp][m0l] = h;     OL[kp][m0l] = l;       \
            split2(v2, v3, h, l); OH[kp][m0l + 8] = h; OL[kp][m0l + 8] = l;   \
        }                                                                     \
    }

    EP_COMPUTE(XH, XL, W1h, W1l)       // layer 1
    EP_STORE(YH, YL, 0)
    __syncwarp();
    EP_COMPUTE(YH, YL, W2h, W2l)       // layer 2
    EP_STORE(XH, XL, 32)
    __syncwarp();
    EP_COMPUTE(XH, XL, W3h, W3l)       // layer 3 (no activation; raw contribution)

#undef EP_COMPUTE
#undef EP_STORE

    // ---- epilogue: pre = P3 + P_a[row] + P_b[col] + bp1; out = relu@Wp2+bp2
    const int r0n = sRow[m0l],     c0n = sCol[m0l];
    const int r1n = sRow[m0l + 8], c1n = sCol[m0l + 8];
    float acc_r0 = 0.f, acc_r1 = 0.f;
#pragma unroll
    for (int nf = 0; nf < 4; ++nf) {
        int j0 = nf * 8 + 2 * tig;
        float2 pa0 = *(const float2*)&g_p[(size_t)r0n * 64 + j0];
        float2 pb0 = *(const float2*)&g_p[(size_t)c0n * 64 + 32 + j0];
        float2 pa1 = *(const float2*)&g_p[(size_t)r1n * 64 + j0];
        float2 pb1 = *(const float2*)&g_p[(size_t)c1n * 64 + 32 + j0];
        float b0 = bp1[j0], b1 = bp1[j0 + 1];
        float w0 = Wp2[j0], w1 = Wp2[j0 + 1];
        float h;
        h = acc[nf][0] + pa0.x + pb0.x + b0; acc_r0 += fmaxf(h, 0.f) * w0;
        h = acc[nf][1] + pa0.y + pb0.y + b1; acc_r0 += fmaxf(h, 0.f) * w1;
        h = acc[nf][2] + pa1.x + pb1.x + b0; acc_r1 += fmaxf(h, 0.f) * w0;
        h = acc[nf][3] + pa1.y + pb1.y + b1; acc_r1 += fmaxf(h, 0.f) * w1;
    }
    acc_r0 += __shfl_xor_sync(0xffffffffu, acc_r0, 1);
    acc_r0 += __shfl_xor_sync(0xffffffffu, acc_r0, 2);
    acc_r1 += __shfl_xor_sync(0xffffffffu, acc_r1, 1);
    acc_r1 += __shfl_xor_sync(0xffffffffu, acc_r1, 2);
    if (tig == 0) {
        float bias2 = bp2[0];
        out[e0 + m0l]     = acc_r0 + bias2;
        out[e0 + m0l + 8] = acc_r1 + bias2;
    }
}

// ---------------- host ----------------
extern "C" void kernel_launch(void* const* d_in, const int* in_sizes, int n_in,
                              void* d_out, int out_size)
{
    const float* x   = (const float*)d_in[0];
    const int*   ei  = (const int*)d_in[1];
    const float* ea  = (const float*)d_in[2];
    const float* W1  = (const float*)d_in[3];
    const float* as1 = (const float*)d_in[4];
    const float* ad1 = (const float*)d_in[5];
    const float* b1  = (const float*)d_in[6];
    const float* W2  = (const float*)d_in[7];
    const float* as2 = (const float*)d_in[8];
    const float* ad2 = (const float*)d_in[9];
    const float* b2  = (const float*)d_in[10];
    const float* Wm1 = (const float*)d_in[11];
    const float* bm1 = (const float*)d_in[12];
    const float* Wm2 = (const float*)d_in[13];
    const float* bm2 = (const float*)d_in[14];
    const float* Wp1 = (const float*)d_in[15];
    const float* bp1 = (const float*)d_in[16];
    const float* Wp2 = (const float*)d_in[17];
    const float* bp2 = (const float*)d_in[18];
    float* out = (float*)d_out;

    float *ph = nullptr, *px = nullptr, *pw = nullptr, *pp = nullptr;
    cudaGetSymbolAddress((void**)&ph, g_h);
    cudaGetSymbolAddress((void**)&px, g_x);
    cudaGetSymbolAddress((void**)&pw, g_wcat);
    cudaGetSymbolAddress((void**)&pp, g_p);

    const int EB  = (N_EDGES + 255) / 256;
    const int NB  = (N_NODES + 255) / 256;
    const int NWB = (N_NODES + 7) / 8;

    // ---- CSR build (once; reused by both layers) ----
    zero_cnt_kernel<<<NB, 256>>>();
    count_kernel<<<EB, 256>>>(ei);
    scan1_kernel<<<NB, 256>>>();
    scan2_kernel<<<1, 256>>>(NB);
    scan3_kernel<<<NB, 256>>>();
    scatter_kernel<<<EB, 256>>>(ei);

    for (int layer = 0; layer < 2; ++layer) {
        const float* X   = layer ? px : x;
        const int    K   = layer ? 256 : 128;
        const float* W   = layer ? W2 : W1;
        const float* as_ = layer ? as2 : as1;
        const float* ad_ = layer ? ad2 : ad1;
        const float* b_  = layer ? b2 : b1;

        tc_gemm_kernel<<<dim3(391, 4), 256>>>(X, W, ph, N_NODES, K, 256, 256, as_, ad_);
        gat_gather_kernel<<<NWB, 256>>>(b_);
    }
    pack_wcat_kernel<<<64, 256>>>(Wp1);
    tc_gemm_kernel<<<dim3(391, 1), 256>>>(px, pw, pp, N_NODES, 256, 64, 64,
                                          nullptr, nullptr);
    edge_pred_kernel<<<N_EDGES / 64, 128>>>(ei, ea,
                                            Wm1, bm1, Wm2, bm2,
                                            Wp1, bp1, Wp2, bp2, out);
}

// round 14
// speedup vs baseline: 1.2642x; 1.0586x over previous
#include <cuda_runtime.h>
#include <cuda_bf16.h>
#include <math.h>

#define N_NODES 50000
#define N_EDGES 400000
#define HEADS 8
#define HID 32
#define F 256            // HEADS*HID
#define NEG 0.2f

// ---------------- scratch (device globals: allocation-free) ----------------
__device__ float g_h[N_NODES * F];        // X @ W (pre-attention features)
__device__ float g_x[N_NODES * F];        // layer output
__device__ float g_asrc[N_NODES * HEADS];
__device__ float g_adst[N_NODES * HEADS];
__device__ float g_p[N_NODES * 64];       // [P_a | P_b] node projections
__device__ float g_wcat[256 * 64];        // [Wp1_a | Wp1_b] packed
__device__ int   g_cnt[N_NODES];
__device__ int   g_off[N_NODES + 1];
__device__ int   g_fill[N_NODES];
__device__ int   g_bsum[256];
__device__ int   g_csrc[N_EDGES];

__device__ __forceinline__ float leaky(float x) { return x > 0.f ? x : NEG * x; }

// pack two floats to bf16x2 (x in low half = first k element)
__device__ __forceinline__ unsigned pk(float x, float y) {
    __nv_bfloat162 h = __floats2bfloat162_rn(x, y);
    return *(unsigned*)&h;
}
__device__ __forceinline__ void split2(float x, float y, unsigned& hi, unsigned& lo) {
    float hx = __bfloat162float(__float2bfloat16_rn(x));
    float hy = __bfloat162float(__float2bfloat16_rn(y));
    hi = pk(hx, hy);
    lo = pk(x - hx, y - hy);
}

__device__ __forceinline__ void mma16(float* c,
    unsigned a0, unsigned a1, unsigned a2, unsigned a3,
    unsigned b0, unsigned b1)
{
    asm volatile(
        "mma.sync.aligned.m16n8k16.row.col.f32.bf16.bf16.f32 "
        "{%0,%1,%2,%3}, {%4,%5,%6,%7}, {%8,%9}, {%0,%1,%2,%3};"
        : "+f"(c[0]), "+f"(c[1]), "+f"(c[2]), "+f"(c[3])
        : "r"(a0), "r"(a1), "r"(a2), "r"(a3), "r"(b0), "r"(b1));
}

// ------ layer GEMM: tile 128x128, BK=16, 3x bf16 split, attention epilogue -
// 256 threads = 8 warps (4 warp_m x 2 warp_n), warp tile 32x64 (2 heads).
__global__ __launch_bounds__(256) void tc_gemm128_kernel(
    const float* __restrict__ A, const float* __restrict__ B,
    float* __restrict__ C, int M, int K, int ldb, int ldc,
    const float* __restrict__ a_src, const float* __restrict__ a_dst)
{
    __shared__ unsigned Ah[8][132], Al[8][132];
    __shared__ unsigned Bh[8][132], Bl[8][132];
    __shared__ float sAs[128], sAd[128];

    const int tid = threadIdx.x;
    const int lane = tid & 31;
    const int wid = tid >> 5;
    const int warp_m = wid >> 1;          // rows warp_m*32
    const int warp_n = wid & 1;           // cols warp_n*64
    const int tig = lane & 3;
    const int grp = lane >> 2;
    const int m0 = blockIdx.x * 128;
    const int n0 = blockIdx.y * 128;

    if (tid < 128) {
        sAs[tid] = a_src[n0 + tid];
        sAd[tid] = a_dst[n0 + tid];
    }

    // A-load coords: two 128-row fragments, 4 consecutive k each
    const int am0 = tid >> 2;             // 0..63
    const int am1 = am0 + 64;             // 64..127
    const int akp = (tid & 3) * 2;
    // B-load coords: n = tid&127, 4 k-pairs {bkh, bkh+2, bkh+4, bkh+6}
    const int bn = tid & 127;
    const int bkh = tid >> 7;             // 0 or 1

    float acc[2][8][4];
#pragma unroll
    for (int mf = 0; mf < 2; ++mf)
#pragma unroll
        for (int nf = 0; nf < 8; ++nf)
#pragma unroll
            for (int j = 0; j < 4; ++j) acc[mf][nf][j] = 0.f;

    // ---- prologue: prefetch tile 0 ----
    float4 va0 = make_float4(0.f, 0.f, 0.f, 0.f);
    float4 va1 = make_float4(0.f, 0.f, 0.f, 0.f);
    float pb[8];
    if (m0 + am0 < M) va0 = *(const float4*)&A[(size_t)(m0 + am0) * K + akp * 2];
    if (m0 + am1 < M) va1 = *(const float4*)&A[(size_t)(m0 + am1) * K + akp * 2];
#pragma unroll
    for (int q = 0; q < 4; ++q) {
        int kp = bkh + 2 * q;
        pb[2 * q]     = B[(size_t)(2 * kp) * ldb + n0 + bn];
        pb[2 * q + 1] = B[(size_t)(2 * kp + 1) * ldb + n0 + bn];
    }

    for (int k0 = 0; k0 < K; k0 += 16) {
        {
            unsigned h, l;
            split2(va0.x, va0.y, h, l); Ah[akp][am0] = h;     Al[akp][am0] = l;
            split2(va0.z, va0.w, h, l); Ah[akp + 1][am0] = h; Al[akp + 1][am0] = l;
            split2(va1.x, va1.y, h, l); Ah[akp][am1] = h;     Al[akp][am1] = l;
            split2(va1.z, va1.w, h, l); Ah[akp + 1][am1] = h; Al[akp + 1][am1] = l;
#pragma unroll
            for (int q = 0; q < 4; ++q) {
                int kp = bkh + 2 * q;
                split2(pb[2 * q], pb[2 * q + 1], h, l);
                Bh[kp][bn] = h; Bl[kp][bn] = l;
            }
        }
        __syncthreads();

        // prefetch next tile (overlapped with MMAs)
        if (k0 + 16 < K) {
            va0 = make_float4(0.f, 0.f, 0.f, 0.f);
            va1 = make_float4(0.f, 0.f, 0.f, 0.f);
            if (m0 + am0 < M) va0 = *(const float4*)&A[(size_t)(m0 + am0) * K + k0 + 16 + akp * 2];
            if (m0 + am1 < M) va1 = *(const float4*)&A[(size_t)(m0 + am1) * K + k0 + 16 + akp * 2];
#pragma unroll
            for (int q = 0; q < 4; ++q) {
                int kp = bkh + 2 * q;
                pb[2 * q]     = B[(size_t)(k0 + 16 + 2 * kp) * ldb + n0 + bn];
                pb[2 * q + 1] = B[(size_t)(k0 + 16 + 2 * kp + 1) * ldb + n0 + bn];
            }
        }

        unsigned ah[2][4], al_[2][4];
#pragma unroll
        for (int mf = 0; mf < 2; ++mf) {
            int mb = warp_m * 32 + mf * 16 + grp;
            ah[mf][0] = Ah[tig][mb];      al_[mf][0] = Al[tig][mb];
            ah[mf][1] = Ah[tig][mb + 8];  al_[mf][1] = Al[tig][mb + 8];
            ah[mf][2] = Ah[tig + 4][mb];      al_[mf][2] = Al[tig + 4][mb];
            ah[mf][3] = Ah[tig + 4][mb + 8];  al_[mf][3] = Al[tig + 4][mb + 8];
        }
#pragma unroll
        for (int nf = 0; nf < 8; ++nf) {
            int n = warp_n * 64 + nf * 8 + grp;
            unsigned bh0 = Bh[tig][n], bh1 = Bh[tig + 4][n];
            unsigned bl0 = Bl[tig][n], bl1 = Bl[tig + 4][n];
#pragma unroll
            for (int mf = 0; mf < 2; ++mf) {
                mma16(acc[mf][nf], ah[mf][0], ah[mf][1], ah[mf][2], ah[mf][3], bh0, bh1);
                mma16(acc[mf][nf], al_[mf][0], al_[mf][1], al_[mf][2], al_[mf][3], bh0, bh1);
                mma16(acc[mf][nf], ah[mf][0], ah[mf][1], ah[mf][2], ah[mf][3], bl0, bl1);
            }
        }
        __syncthreads();
    }

    // ---- store C ----
#pragma unroll
    for (int mf = 0; mf < 2; ++mf) {
        int r0 = m0 + warp_m * 32 + mf * 16 + grp;
        int r1 = r0 + 8;
#pragma unroll
        for (int nf = 0; nf < 8; ++nf) {
            int c = n0 + warp_n * 64 + nf * 8 + tig * 2;
            if (r0 < M)
                *(float2*)&C[(size_t)r0 * ldc + c] = make_float2(acc[mf][nf][0], acc[mf][nf][1]);
            if (r1 < M)
                *(float2*)&C[(size_t)r1 * ldc + c] = make_float2(acc[mf][nf][2], acc[mf][nf][3]);
        }
    }

    // ---- attention dots: warp spans 2 heads (nf 0..3 and nf 4..7) ----
#pragma unroll
    for (int mf = 0; mf < 2; ++mf) {
#pragma unroll
        for (int half = 0; half < 2; ++half) {
            const int head = (n0 >> 5) + warp_n * 2 + half;
            float ps0 = 0.f, pd0 = 0.f, ps1 = 0.f, pd1 = 0.f;
#pragma unroll
            for (int q = 0; q < 4; ++q) {
                int nf = half * 4 + q;
                int cl = warp_n * 64 + nf * 8 + tig * 2;
                float w0s = sAs[cl], w1s = sAs[cl + 1];
                float w0d = sAd[cl], w1d = sAd[cl + 1];
                ps0 += acc[mf][nf][0] * w0s + acc[mf][nf][1] * w1s;
                pd0 += acc[mf][nf][0] * w0d + acc[mf][nf][1] * w1d;
                ps1 += acc[mf][nf][2] * w0s + acc[mf][nf][3] * w1s;
                pd1 += acc[mf][nf][2] * w0d + acc[mf][nf][3] * w1d;
            }
#pragma unroll
            for (int off = 1; off <= 2; off <<= 1) {
                ps0 += __shfl_xor_sync(0xffffffffu, ps0, off);
                pd0 += __shfl_xor_sync(0xffffffffu, pd0, off);
                ps1 += __shfl_xor_sync(0xffffffffu, ps1, off);
                pd1 += __shfl_xor_sync(0xffffffffu, pd1, off);
            }
            if (tig == 0) {
                int r0 = m0 + warp_m * 32 + mf * 16 + grp;
                int r1 = r0 + 8;
                if (r0 < M) { g_asrc[r0 * 8 + head] = ps0; g_adst[r0 * 8 + head] = pd0; }
                if (r1 < M) { g_asrc[r1 * 8 + head] = ps1; g_adst[r1 * 8 + head] = pd1; }
            }
        }
    }
}

// ------ proj GEMM: tile 128x64, BK=16 (round-12 verified kernel) -----------
__global__ __launch_bounds__(256) void tc_gemm_kernel(
    const float* __restrict__ A, const float* __restrict__ B,
    float* __restrict__ C, int M, int K, int ldb, int ldc)
{
    __shared__ unsigned Ah[8][132], Al[8][132];
    __shared__ unsigned Bh[8][68],  Bl[8][68];

    const int tid = threadIdx.x;
    const int lane = tid & 31;
    const int wid = tid >> 5;
    const int warp_m = wid >> 1;
    const int warp_n = wid & 1;
    const int tig = lane & 3;
    const int grp = lane >> 2;
    const int m0 = blockIdx.x * 128;
    const int n0 = blockIdx.y * 64;

    const int am0 = tid >> 2;
    const int am1 = am0 + 64;
    const int akp = (tid & 3) * 2;
    const int bn = tid & 63;
    const int bkh = tid >> 6;

    float acc[2][4][4];
#pragma unroll
    for (int mf = 0; mf < 2; ++mf)
#pragma unroll
        for (int nf = 0; nf < 4; ++nf)
#pragma unroll
            for (int j = 0; j < 4; ++j) acc[mf][nf][j] = 0.f;

    float4 va0 = make_float4(0.f, 0.f, 0.f, 0.f);
    float4 va1 = make_float4(0.f, 0.f, 0.f, 0.f);
    float pb0, pb1, pb2, pb3;
    if (m0 + am0 < M) va0 = *(const float4*)&A[(size_t)(m0 + am0) * K + akp * 2];
    if (m0 + am1 < M) va1 = *(const float4*)&A[(size_t)(m0 + am1) * K + akp * 2];
    pb0 = B[(size_t)(2 * bkh) * ldb + n0 + bn];
    pb1 = B[(size_t)(2 * bkh + 1) * ldb + n0 + bn];
    pb2 = B[(size_t)(2 * (bkh + 4)) * ldb + n0 + bn];
    pb3 = B[(size_t)(2 * (bkh + 4) + 1) * ldb + n0 + bn];

    for (int k0 = 0; k0 < K; k0 += 16) {
        {
            unsigned h, l;
            split2(va0.x, va0.y, h, l); Ah[akp][am0] = h;     Al[akp][am0] = l;
            split2(va0.z, va0.w, h, l); Ah[akp + 1][am0] = h; Al[akp + 1][am0] = l;
            split2(va1.x, va1.y, h, l); Ah[akp][am1] = h;     Al[akp][am1] = l;
            split2(va1.z, va1.w, h, l); Ah[akp + 1][am1] = h; Al[akp + 1][am1] = l;
            split2(pb0, pb1, h, l); Bh[bkh][bn] = h;     Bl[bkh][bn] = l;
            split2(pb2, pb3, h, l); Bh[bkh + 4][bn] = h; Bl[bkh + 4][bn] = l;
        }
        __syncthreads();

        if (k0 + 16 < K) {
            va0 = make_float4(0.f, 0.f, 0.f, 0.f);
            va1 = make_float4(0.f, 0.f, 0.f, 0.f);
            if (m0 + am0 < M) va0 = *(const float4*)&A[(size_t)(m0 + am0) * K + k0 + 16 + akp * 2];
            if (m0 + am1 < M) va1 = *(const float4*)&A[(size_t)(m0 + am1) * K + k0 + 16 + akp * 2];
            pb0 = B[(size_t)(k0 + 16 + 2 * bkh) * ldb + n0 + bn];
            pb1 = B[(size_t)(k0 + 16 + 2 * bkh + 1) * ldb + n0 + bn];
            pb2 = B[(size_t)(k0 + 16 + 2 * (bkh + 4)) * ldb + n0 + bn];
            pb3 = B[(size_t)(k0 + 16 + 2 * (bkh + 4) + 1) * ldb + n0 + bn];
        }

        unsigned ah[2][4], al_[2][4];
#pragma unroll
        for (int mf = 0; mf < 2; ++mf) {
            int mb = warp_m * 32 + mf * 16 + grp;
            ah[mf][0] = Ah[tig][mb];      al_[mf][0] = Al[tig][mb];
            ah[mf][1] = Ah[tig][mb + 8];  al_[mf][1] = Al[tig][mb + 8];
            ah[mf][2] = Ah[tig + 4][mb];      al_[mf][2] = Al[tig + 4][mb];
            ah[mf][3] = Ah[tig + 4][mb + 8];  al_[mf][3] = Al[tig + 4][mb + 8];
        }
#pragma unroll
        for (int nf = 0; nf < 4; ++nf) {
            int n = warp_n * 32 + nf * 8 + grp;
            unsigned bh0 = Bh[tig][n], bh1 = Bh[tig + 4][n];
            unsigned bl0 = Bl[tig][n], bl1 = Bl[tig + 4][n];
#pragma unroll
            for (int mf = 0; mf < 2; ++mf) {
                mma16(acc[mf][nf], ah[mf][0], ah[mf][1], ah[mf][2], ah[mf][3], bh0, bh1);
                mma16(acc[mf][nf], al_[mf][0], al_[mf][1], al_[mf][2], al_[mf][3], bh0, bh1);
                mma16(acc[mf][nf], ah[mf][0], ah[mf][1], ah[mf][2], ah[mf][3], bl0, bl1);
            }
        }
        __syncthreads();
    }

#pragma unroll
    for (int mf = 0; mf < 2; ++mf) {
        int r0 = m0 + warp_m * 32 + mf * 16 + grp;
        int r1 = r0 + 8;
#pragma unroll
        for (int nf = 0; nf < 4; ++nf) {
            int c = n0 + warp_n * 32 + nf * 8 + tig * 2;
            if (r0 < M)
                *(float2*)&C[(size_t)r0 * ldc + c] = make_float2(acc[mf][nf][0], acc[mf][nf][1]);
            if (r1 < M)
                *(float2*)&C[(size_t)r1 * ldc + c] = make_float2(acc[mf][nf][2], acc[mf][nf][3]);
        }
    }
}

// ---------------- CSR build ----------------
__global__ __launch_bounds__(256) void zero_cnt_kernel()
{
    int i = blockIdx.x * blockDim.x + threadIdx.x;
    if (i < N_NODES) g_cnt[i] = 0;
}
__global__ __launch_bounds__(256) void count_kernel(const int* __restrict__ ei)
{
    int e = blockIdx.x * blockDim.x + threadIdx.x;
    if (e < N_EDGES) atomicAdd(&g_cnt[ei[N_EDGES + e]], 1);
}
__global__ __launch_bounds__(256) void scan1_kernel()
{
    __shared__ int sh[256];
    int i = blockIdx.x * 256 + threadIdx.x;
    int v = (i < N_NODES) ? g_cnt[i] : 0;
    sh[threadIdx.x] = v;
    __syncthreads();
#pragma unroll
    for (int off = 1; off < 256; off <<= 1) {
        int t = 0;
        if (threadIdx.x >= off) t = sh[threadIdx.x - off];
        __syncthreads();
        if (threadIdx.x >= off) sh[threadIdx.x] += t;
        __syncthreads();
    }
    if (i < N_NODES) g_off[i + 1] = sh[threadIdx.x];
    if (threadIdx.x == 255) g_bsum[blockIdx.x] = sh[255];
    if (i == 0) g_off[0] = 0;
}
__global__ __launch_bounds__(256) void scan2_kernel(int nblocks)
{
    __shared__ int sh[256];
    int t = threadIdx.x;
    int v = (t < nblocks) ? g_bsum[t] : 0;
    sh[t] = v;
    __syncthreads();
#pragma unroll
    for (int off = 1; off < 256; off <<= 1) {
        int u = 0;
        if (t >= off) u = sh[t - off];
        __syncthreads();
        if (t >= off) sh[t] += u;
        __syncthreads();
    }
    if (t < nblocks) g_bsum[t] = sh[t] - v;    // exclusive
}
__global__ __launch_bounds__(256) void scan3_kernel()
{
    int i = blockIdx.x * 256 + threadIdx.x;
    if (i < N_NODES) {
        int v = g_off[i + 1] + g_bsum[blockIdx.x];
        g_off[i + 1] = v;
        if (i + 1 < N_NODES) g_fill[i + 1] = v;
        if (i == 0) g_fill[0] = 0;
    }
}
__global__ __launch_bounds__(256) void scatter_kernel(const int* __restrict__ ei)
{
    int e = blockIdx.x * blockDim.x + threadIdx.x;
    if (e >= N_EDGES) return;
    int s = ei[e], d = ei[N_EDGES + e];
    int pos = atomicAdd(&g_fill[d], 1);
    g_csrc[pos] = s;
}

// -------- gather attention: one warp per node, fused softmax+agg+relu ------
__global__ __launch_bounds__(256) void gat_gather_kernel(const float* __restrict__ b)
{
    const int warp = threadIdx.x >> 5, lane = threadIdx.x & 31;
    const int n = blockIdx.x * 8 + warp;
    if (n >= N_NODES) return;
    const unsigned FULL = 0xffffffffu;
    const int h0 = lane >> 3, h1 = 4 + (lane >> 3);

    float myasrc = 0.f, myadst = 0.f;
    if (lane < 8) {
        myasrc = g_asrc[n * 8 + lane];
        myadst = g_adst[n * 8 + lane];
    }
    float4 acc0 = make_float4(0.f, 0.f, 0.f, 0.f);
    float4 acc1 = make_float4(0.f, 0.f, 0.f, 0.f);
    float denom = 0.f;

    const int beg = g_off[n], end = g_off[n + 1];
    for (int i = beg; i < end; ++i) {
        int s = g_csrc[i];
        float w = 0.f;
        if (lane < 8) {
            w = expf(leaky(g_asrc[s * 8 + lane] + myadst));
            denom += w;
        }
        float al0 = __shfl_sync(FULL, w, h0);
        float al1 = __shfl_sync(FULL, w, h1);
        float4 v0 = *(const float4*)&g_h[(size_t)s * 256 + lane * 4];
        float4 v1 = *(const float4*)&g_h[(size_t)s * 256 + 128 + lane * 4];
        acc0.x += al0 * v0.x; acc0.y += al0 * v0.y;
        acc0.z += al0 * v0.z; acc0.w += al0 * v0.w;
        acc1.x += al1 * v1.x; acc1.y += al1 * v1.y;
        acc1.z += al1 * v1.z; acc1.w += al1 * v1.w;
    }
    // self loop
    {
        float w = 0.f;
        if (lane < 8) {
            w = expf(leaky(myasrc + myadst));
            denom += w;
        }
        float al0 = __shfl_sync(FULL, w, h0);
        float al1 = __shfl_sync(FULL, w, h1);
        float4 v0 = *(const float4*)&g_h[(size_t)n * 256 + lane * 4];
        float4 v1 = *(const float4*)&g_h[(size_t)n * 256 + 128 + lane * 4];
        acc0.x += al0 * v0.x; acc0.y += al0 * v0.y;
        acc0.z += al0 * v0.z; acc0.w += al0 * v0.w;
        acc1.x += al1 * v1.x; acc1.y += al1 * v1.y;
        acc1.z += al1 * v1.z; acc1.w += al1 * v1.w;
    }
    float inv0 = 1.f / __shfl_sync(FULL, denom, h0);
    float inv1 = 1.f / __shfl_sync(FULL, denom, h1);
    float4 bb0 = *(const float4*)&b[lane * 4];
    float4 bb1 = *(const float4*)&b[128 + lane * 4];
    float4 o0, o1;
    o0.x = fmaxf(acc0.x * inv0 + bb0.x, 0.f);
    o0.y = fmaxf(acc0.y * inv0 + bb0.y, 0.f);
    o0.z = fmaxf(acc0.z * inv0 + bb0.z, 0.f);
    o0.w = fmaxf(acc0.w * inv0 + bb0.w, 0.f);
    o1.x = fmaxf(acc1.x * inv1 + bb1.x, 0.f);
    o1.y = fmaxf(acc1.y * inv1 + bb1.y, 0.f);
    o1.z = fmaxf(acc1.z * inv1 + bb1.z, 0.f);
    o1.w = fmaxf(acc1.w * inv1 + bb1.w, 0.f);
    *(float4*)&g_x[(size_t)n * 256 + lane * 4] = o0;
    *(float4*)&g_x[(size_t)n * 256 + 128 + lane * 4] = o1;
}

// ---------------- pack Wcat = [Wp1_a | Wp1_b] : [256 x 64] ----------------
__global__ __launch_bounds__(256) void pack_wcat_kernel(const float* __restrict__ Wp1)
{
    int i = blockIdx.x * blockDim.x + threadIdx.x;
    if (i >= 256 * 64) return;
    int k = i >> 6, j = i & 63;
    g_wcat[i] = (j < 32) ? Wp1[k * 32 + j] : Wp1[(256 + k) * 32 + (j - 32)];
}

// ------- edge predictor: bf16-split tensor-core edge-MLP + exact combine ---
__global__ __launch_bounds__(128) void edge_pred_kernel(
    const int* __restrict__ ei, const float* __restrict__ edge_attr,
    const float* __restrict__ Wm1, const float* __restrict__ bm1,
    const float* __restrict__ Wm2, const float* __restrict__ bm2,
    const float* __restrict__ Wp1, const float* __restrict__ bp1,
    const float* __restrict__ Wp2, const float* __restrict__ bp2,
    float* __restrict__ out)
{
    __shared__ unsigned XH[16][66], XL[16][66];    // ping buffer
    __shared__ unsigned YH[16][66], YL[16][66];    // pong buffer
    __shared__ unsigned W1h[16][33], W1l[16][33];
    __shared__ unsigned W2h[16][33], W2l[16][33];
    __shared__ unsigned W3h[16][33], W3l[16][33];
    __shared__ int   sRow[64], sCol[64];
    __shared__ float sB[64];                       // bm1 | bm2

    const int tid = threadIdx.x;
    const int lane = tid & 31;
    const int wrp = tid >> 5;
    const int tig = lane & 3;
    const int grp = lane >> 2;
    const int e0 = blockIdx.x * 64;
    const int m0l = wrp * 16 + grp;                // local edge row (0..63)

    if (tid < 64) {
        sRow[tid] = ei[e0 + tid];
        sCol[tid] = ei[N_EDGES + e0 + tid];
    }
    if (tid < 32) { sB[tid] = bm1[tid]; sB[32 + tid] = bm2[tid]; }

    for (int i = tid; i < 512; i += 128) {
        int kp = i >> 5, n = i & 31;
        unsigned h, l;
        split2(Wm1[(2 * kp) * 32 + n], Wm1[(2 * kp + 1) * 32 + n], h, l);
        W1h[kp][n] = h; W1l[kp][n] = l;
        split2(Wm2[(2 * kp) * 32 + n], Wm2[(2 * kp + 1) * 32 + n], h, l);
        W2h[kp][n] = h; W2l[kp][n] = l;
        split2(Wp1[(512 + 2 * kp) * 32 + n], Wp1[(512 + 2 * kp + 1) * 32 + n], h, l);
        W3h[kp][n] = h; W3l[kp][n] = l;
    }
    for (int f = tid; f < 512; f += 128) {
        int e = f >> 3, q = f & 7;
        float4 v = *(const float4*)&edge_attr[(size_t)(e0 + e) * 32 + q * 4];
        unsigned h, l;
        split2(v.x, v.y, h, l); XH[2 * q][e] = h;     XL[2 * q][e] = l;
        split2(v.z, v.w, h, l); XH[2 * q + 1][e] = h; XL[2 * q + 1][e] = l;
    }
    __syncthreads();

    float acc[4][4];

#define EP_COMPUTE(IH, IL, WH, WL)                                            \
    {                                                                         \
        _Pragma("unroll")                                                     \
        for (int nf = 0; nf < 4; ++nf)                                        \
            _Pragma("unroll")                                                 \
            for (int j = 0; j < 4; ++j) acc[nf][j] = 0.f;                     \
        _Pragma("unroll")                                                     \
        for (int ks = 0; ks < 2; ++ks) {                                      \
            int kb = ks * 8;                                                  \
            unsigned a0 = IH[kb + tig][m0l],     l0 = IL[kb + tig][m0l];      \
            unsigned a1 = IH[kb + tig][m0l + 8], l1 = IL[kb + tig][m0l + 8];  \
            unsigned a2 = IH[kb + tig + 4][m0l],     l2 = IL[kb + tig + 4][m0l];     \
            unsigned a3 = IH[kb + tig + 4][m0l + 8], l3 = IL[kb + tig + 4][m0l + 8]; \
            _Pragma("unroll")                                                 \
            for (int nf = 0; nf < 4; ++nf) {                                  \
                int n = nf * 8 + grp;                                         \
                unsigned bh0 = WH[kb + tig][n], bh1 = WH[kb + tig + 4][n];    \
                unsigned bl0 = WL[kb + tig][n], bl1 = WL[kb + tig + 4][n];    \
                mma16(acc[nf], a0, a1, a2, a3, bh0, bh1);                     \
                mma16(acc[nf], l0, l1, l2, l3, bh0, bh1);                     \
                mma16(acc[nf], a0, a1, a2, a3, bl0, bl1);                     \
            }                                                                 \
        }                                                                     \
    }
#define EP_STORE(OH, OL, boff)                                                \
    {                                                                         \
        _Pragma("unroll")                                                     \
        for (int nf = 0; nf < 4; ++nf) {                                      \
            int j0 = nf * 8 + 2 * tig;                                        \
            int kp = nf * 4 + tig;                                            \
            float b0 = sB[boff + j0], b1 = sB[boff + j0 + 1];                 \
            float v0 = fmaxf(acc[nf][0] + b0, 0.f);                           \
            float v1 = fmaxf(acc[nf][1] + b1, 0.f);                           \
            float v2 = fmaxf(acc[nf][2] + b0, 0.f);                           \
            float v3 = fmaxf(acc[nf][3] + b1, 0.f);                           \
            unsigned h, l;                                                    \
            split2(v0, v1, h, l); OH[kp][m0l] = h;     OL[kp][m0l] = l;       \
            split2(v2, v3, h, l); OH[kp][m0l + 8] = h; OL[kp][m0l + 8] = l;   \
        }                                                                     \
    }

    EP_COMPUTE(XH, XL, W1h, W1l)
    EP_STORE(YH, YL, 0)
    __syncwarp();
    EP_COMPUTE(YH, YL, W2h, W2l)
    EP_STORE(XH, XL, 32)
    __syncwarp();
    EP_COMPUTE(XH, XL, W3h, W3l)

#undef EP_COMPUTE
#undef EP_STORE

    const int r0n = sRow[m0l],     c0n = sCol[m0l];
    const int r1n = sRow[m0l + 8], c1n = sCol[m0l + 8];
    float acc_r0 = 0.f, acc_r1 = 0.f;
#pragma unroll
    for (int nf = 0; nf < 4; ++nf) {
        int j0 = nf * 8 + 2 * tig;
        float2 pa0 = *(const float2*)&g_p[(size_t)r0n * 64 + j0];
        float2 pb0 = *(const float2*)&g_p[(size_t)c0n * 64 + 32 + j0];
        float2 pa1 = *(const float2*)&g_p[(size_t)r1n * 64 + j0];
        float2 pb1 = *(const float2*)&g_p[(size_t)c1n * 64 + 32 + j0];
        float b0 = bp1[j0], b1 = bp1[j0 + 1];
        float w0 = Wp2[j0], w1 = Wp2[j0 + 1];
        float h;
        h = acc[nf][0] + pa0.x + pb0.x + b0; acc_r0 += fmaxf(h, 0.f) * w0;
        h = acc[nf][1] + pa0.y + pb0.y + b1; acc_r0 += fmaxf(h, 0.f) * w1;
        h = acc[nf][2] + pa1.x + pb1.x + b0; acc_r1 += fmaxf(h, 0.f) * w0;
        h = acc[nf][3] + pa1.y + pb1.y + b1; acc_r1 += fmaxf(h, 0.f) * w1;
    }
    acc_r0 += __shfl_xor_sync(0xffffffffu, acc_r0, 1);
    acc_r0 += __shfl_xor_sync(0xffffffffu, acc_r0, 2);
    acc_r1 += __shfl_xor_sync(0xffffffffu, acc_r1, 1);
    acc_r1 += __shfl_xor_sync(0xffffffffu, acc_r1, 2);
    if (tig == 0) {
        float bias2 = bp2[0];
        out[e0 + m0l]     = acc_r0 + bias2;
        out[e0 + m0l + 8] = acc_r1 + bias2;
    }
}

// ---------------- host ----------------
extern "C" void kernel_launch(void* const* d_in, const int* in_sizes, int n_in,
                              void* d_out, int out_size)
{
    const float* x   = (const float*)d_in[0];
    const int*   ei  = (const int*)d_in[1];
    const float* ea  = (const float*)d_in[2];
    const float* W1  = (const float*)d_in[3];
    const float* as1 = (const float*)d_in[4];
    const float* ad1 = (const float*)d_in[5];
    const float* b1  = (const float*)d_in[6];
    const float* W2  = (const float*)d_in[7];
    const float* as2 = (const float*)d_in[8];
    const float* ad2 = (const float*)d_in[9];
    const float* b2  = (const float*)d_in[10];
    const float* Wm1 = (const float*)d_in[11];
    const float* bm1 = (const float*)d_in[12];
    const float* Wm2 = (const float*)d_in[13];
    const float* bm2 = (const float*)d_in[14];
    const float* Wp1 = (const float*)d_in[15];
    const float* bp1 = (const float*)d_in[16];
    const float* Wp2 = (const float*)d_in[17];
    const float* bp2 = (const float*)d_in[18];
    float* out = (float*)d_out;

    float *ph = nullptr, *px = nullptr, *pw = nullptr, *pp = nullptr;
    cudaGetSymbolAddress((void**)&ph, g_h);
    cudaGetSymbolAddress((void**)&px, g_x);
    cudaGetSymbolAddress((void**)&pw, g_wcat);
    cudaGetSymbolAddress((void**)&pp, g_p);

    const int EB  = (N_EDGES + 255) / 256;
    const int NB  = (N_NODES + 255) / 256;
    const int NWB = (N_NODES + 7) / 8;

    // ---- CSR build (once; reused by both layers) ----
    zero_cnt_kernel<<<NB, 256>>>();
    count_kernel<<<EB, 256>>>(ei);
    scan1_kernel<<<NB, 256>>>();
    scan2_kernel<<<1, 256>>>(NB);
    scan3_kernel<<<NB, 256>>>();
    scatter_kernel<<<EB, 256>>>(ei);

    for (int layer = 0; layer < 2; ++layer) {
        const float* X   = layer ? px : x;
        const int    K   = layer ? 256 : 128;
        const float* W   = layer ? W2 : W1;
        const float* as_ = layer ? as2 : as1;
        const float* ad_ = layer ? ad2 : ad1;
        const float* b_  = layer ? b2 : b1;

        tc_gemm128_kernel<<<dim3(391, 2), 256>>>(X, W, ph, N_NODES, K, 256, 256, as_, ad_);
        gat_gather_kernel<<<NWB, 256>>>(b_);
    }
    pack_wcat_kernel<<<64, 256>>>(Wp1);
    tc_gemm_kernel<<<dim3(391, 1), 256>>>(px, pw, pp, N_NODES, 256, 64, 64);
    edge_pred_kernel<<<N_EDGES / 64, 128>>>(ei, ea,
                                            Wm1, bm1, Wm2, bm2,
                                            Wp1, bp1, Wp2, bp2, out);
}

// round 15
// speedup vs baseline: 1.2710x; 1.0054x over previous
#include <cuda_runtime.h>
#include <cuda_bf16.h>
#include <math.h>

#define N_NODES 50000
#define N_EDGES 400000
#define HEADS 8
#define HID 32
#define F 256            // HEADS*HID
#define NEG 0.2f

// ---------------- scratch (device globals: allocation-free) ----------------
__device__ float g_h[N_NODES * F];        // X @ W (pre-attention features)
__device__ float g_x[N_NODES * F];        // layer output
__device__ float g_asrc[N_NODES * HEADS];
__device__ float g_adst[N_NODES * HEADS];
__device__ float g_p[N_NODES * 64];       // [P_a | P_b] node projections
__device__ float g_wcat[256 * 64];        // [Wp1_a | Wp1_b] packed
__device__ int   g_cnt[N_NODES];
__device__ int   g_off[N_NODES + 1];
__device__ int   g_fill[N_NODES];
__device__ int   g_bsum[256];
__device__ int   g_csrc[N_EDGES];

__device__ __forceinline__ float leaky(float x) { return x > 0.f ? x : NEG * x; }

// pack two floats to bf16x2 (x in low half = first k element)
__device__ __forceinline__ unsigned pk(float x, float y) {
    __nv_bfloat162 h = __floats2bfloat162_rn(x, y);
    return *(unsigned*)&h;
}
__device__ __forceinline__ void split2(float x, float y, unsigned& hi, unsigned& lo) {
    float hx = __bfloat162float(__float2bfloat16_rn(x));
    float hy = __bfloat162float(__float2bfloat16_rn(y));
    hi = pk(hx, hy);
    lo = pk(x - hx, y - hy);
}

__device__ __forceinline__ void mma16(float* c,
    unsigned a0, unsigned a1, unsigned a2, unsigned a3,
    unsigned b0, unsigned b1)
{
    asm volatile(
        "mma.sync.aligned.m16n8k16.row.col.f32.bf16.bf16.f32 "
        "{%0,%1,%2,%3}, {%4,%5,%6,%7}, {%8,%9}, {%0,%1,%2,%3};"
        : "+f"(c[0]), "+f"(c[1]), "+f"(c[2]), "+f"(c[3])
        : "r"(a0), "r"(a1), "r"(a2), "r"(a3), "r"(b0), "r"(b1));
}

// ------ layer GEMM: tile 128x128, BK=16, 3x bf16 split, attention epilogue -
// 256 threads = 8 warps (4 warp_m x 2 warp_n), warp tile 32x64 (2 heads).
// Smem double-buffered: ONE __syncthreads per k-tile (store -> sync -> MMA,
// next store goes to the alternate buffer; the iter i+1 barrier separates the
// iter i read of buffer p from the iter i+2 write of p).
__global__ __launch_bounds__(256) void tc_gemm128_kernel(
    const float* __restrict__ A, const float* __restrict__ B,
    float* __restrict__ C, int M, int K, int ldb, int ldc,
    const float* __restrict__ a_src, const float* __restrict__ a_dst)
{
    __shared__ unsigned Ah[2][8][132], Al[2][8][132];
    __shared__ unsigned Bh[2][8][132], Bl[2][8][132];
    __shared__ float sAs[128], sAd[128];

    const int tid = threadIdx.x;
    const int lane = tid & 31;
    const int wid = tid >> 5;
    const int warp_m = wid >> 1;          // rows warp_m*32
    const int warp_n = wid & 1;           // cols warp_n*64
    const int tig = lane & 3;
    const int grp = lane >> 2;
    const int m0 = blockIdx.x * 128;
    const int n0 = blockIdx.y * 128;

    if (tid < 128) {
        sAs[tid] = a_src[n0 + tid];
        sAd[tid] = a_dst[n0 + tid];
    }

    const int am0 = tid >> 2;             // 0..63
    const int am1 = am0 + 64;             // 64..127
    const int akp = (tid & 3) * 2;
    const int bn = tid & 127;
    const int bkh = tid >> 7;             // 0 or 1

    float acc[2][8][4];
#pragma unroll
    for (int mf = 0; mf < 2; ++mf)
#pragma unroll
        for (int nf = 0; nf < 8; ++nf)
#pragma unroll
            for (int j = 0; j < 4; ++j) acc[mf][nf][j] = 0.f;

    // ---- prologue: prefetch tile 0 ----
    float4 va0 = make_float4(0.f, 0.f, 0.f, 0.f);
    float4 va1 = make_float4(0.f, 0.f, 0.f, 0.f);
    float pb[8];
    if (m0 + am0 < M) va0 = *(const float4*)&A[(size_t)(m0 + am0) * K + akp * 2];
    if (m0 + am1 < M) va1 = *(const float4*)&A[(size_t)(m0 + am1) * K + akp * 2];
#pragma unroll
    for (int q = 0; q < 4; ++q) {
        int kp = bkh + 2 * q;
        pb[2 * q]     = B[(size_t)(2 * kp) * ldb + n0 + bn];
        pb[2 * q + 1] = B[(size_t)(2 * kp + 1) * ldb + n0 + bn];
    }

    int buf = 0;
    for (int k0 = 0; k0 < K; k0 += 16) {
        // ---- split current registers into smem buffer `buf` ----
        {
            unsigned h, l;
            split2(va0.x, va0.y, h, l); Ah[buf][akp][am0] = h;     Al[buf][akp][am0] = l;
            split2(va0.z, va0.w, h, l); Ah[buf][akp + 1][am0] = h; Al[buf][akp + 1][am0] = l;
            split2(va1.x, va1.y, h, l); Ah[buf][akp][am1] = h;     Al[buf][akp][am1] = l;
            split2(va1.z, va1.w, h, l); Ah[buf][akp + 1][am1] = h; Al[buf][akp + 1][am1] = l;
#pragma unroll
            for (int q = 0; q < 4; ++q) {
                int kp = bkh + 2 * q;
                split2(pb[2 * q], pb[2 * q + 1], h, l);
                Bh[buf][kp][bn] = h; Bl[buf][kp][bn] = l;
            }
        }
        __syncthreads();

        // ---- prefetch next tile into registers (overlapped with MMAs) ----
        if (k0 + 16 < K) {
            va0 = make_float4(0.f, 0.f, 0.f, 0.f);
            va1 = make_float4(0.f, 0.f, 0.f, 0.f);
            if (m0 + am0 < M) va0 = *(const float4*)&A[(size_t)(m0 + am0) * K + k0 + 16 + akp * 2];
            if (m0 + am1 < M) va1 = *(const float4*)&A[(size_t)(m0 + am1) * K + k0 + 16 + akp * 2];
#pragma unroll
            for (int q = 0; q < 4; ++q) {
                int kp = bkh + 2 * q;
                pb[2 * q]     = B[(size_t)(k0 + 16 + 2 * kp) * ldb + n0 + bn];
                pb[2 * q + 1] = B[(size_t)(k0 + 16 + 2 * kp + 1) * ldb + n0 + bn];
            }
        }

        unsigned ah[2][4], al_[2][4];
#pragma unroll
        for (int mf = 0; mf < 2; ++mf) {
            int mb = warp_m * 32 + mf * 16 + grp;
            ah[mf][0] = Ah[buf][tig][mb];      al_[mf][0] = Al[buf][tig][mb];
            ah[mf][1] = Ah[buf][tig][mb + 8];  al_[mf][1] = Al[buf][tig][mb + 8];
            ah[mf][2] = Ah[buf][tig + 4][mb];      al_[mf][2] = Al[buf][tig + 4][mb];
            ah[mf][3] = Ah[buf][tig + 4][mb + 8];  al_[mf][3] = Al[buf][tig + 4][mb + 8];
        }
#pragma unroll
        for (int nf = 0; nf < 8; ++nf) {
            int n = warp_n * 64 + nf * 8 + grp;
            unsigned bh0 = Bh[buf][tig][n], bh1 = Bh[buf][tig + 4][n];
            unsigned bl0 = Bl[buf][tig][n], bl1 = Bl[buf][tig + 4][n];
#pragma unroll
            for (int mf = 0; mf < 2; ++mf) {
                mma16(acc[mf][nf], ah[mf][0], ah[mf][1], ah[mf][2], ah[mf][3], bh0, bh1);
                mma16(acc[mf][nf], al_[mf][0], al_[mf][1], al_[mf][2], al_[mf][3], bh0, bh1);
                mma16(acc[mf][nf], ah[mf][0], ah[mf][1], ah[mf][2], ah[mf][3], bl0, bl1);
            }
        }
        buf ^= 1;        // next store targets the other buffer — no trailing sync
    }

    // ---- store C ----
#pragma unroll
    for (int mf = 0; mf < 2; ++mf) {
        int r0 = m0 + warp_m * 32 + mf * 16 + grp;
        int r1 = r0 + 8;
#pragma unroll
        for (int nf = 0; nf < 8; ++nf) {
            int c = n0 + warp_n * 64 + nf * 8 + tig * 2;
            if (r0 < M)
                *(float2*)&C[(size_t)r0 * ldc + c] = make_float2(acc[mf][nf][0], acc[mf][nf][1]);
            if (r1 < M)
                *(float2*)&C[(size_t)r1 * ldc + c] = make_float2(acc[mf][nf][2], acc[mf][nf][3]);
        }
    }

    // ---- attention dots: warp spans 2 heads (nf 0..3 and nf 4..7) ----
#pragma unroll
    for (int mf = 0; mf < 2; ++mf) {
#pragma unroll
        for (int half = 0; half < 2; ++half) {
            const int head = (n0 >> 5) + warp_n * 2 + half;
            float ps0 = 0.f, pd0 = 0.f, ps1 = 0.f, pd1 = 0.f;
#pragma unroll
            for (int q = 0; q < 4; ++q) {
                int nf = half * 4 + q;
                int cl = warp_n * 64 + nf * 8 + tig * 2;
                float w0s = sAs[cl], w1s = sAs[cl + 1];
                float w0d = sAd[cl], w1d = sAd[cl + 1];
                ps0 += acc[mf][nf][0] * w0s + acc[mf][nf][1] * w1s;
                pd0 += acc[mf][nf][0] * w0d + acc[mf][nf][1] * w1d;
                ps1 += acc[mf][nf][2] * w0s + acc[mf][nf][3] * w1s;
                pd1 += acc[mf][nf][2] * w0d + acc[mf][nf][3] * w1d;
            }
#pragma unroll
            for (int off = 1; off <= 2; off <<= 1) {
                ps0 += __shfl_xor_sync(0xffffffffu, ps0, off);
                pd0 += __shfl_xor_sync(0xffffffffu, pd0, off);
                ps1 += __shfl_xor_sync(0xffffffffu, ps1, off);
                pd1 += __shfl_xor_sync(0xffffffffu, pd1, off);
            }
            if (tig == 0) {
                int r0 = m0 + warp_m * 32 + mf * 16 + grp;
                int r1 = r0 + 8;
                if (r0 < M) { g_asrc[r0 * 8 + head] = ps0; g_adst[r0 * 8 + head] = pd0; }
                if (r1 < M) { g_asrc[r1 * 8 + head] = ps1; g_adst[r1 * 8 + head] = pd1; }
            }
        }
    }
}

// ------ proj GEMM: tile 128x64, BK=16 (round-12 verified kernel) -----------
__global__ __launch_bounds__(256) void tc_gemm_kernel(
    const float* __restrict__ A, const float* __restrict__ B,
    float* __restrict__ C, int M, int K, int ldb, int ldc)
{
    __shared__ unsigned Ah[8][132], Al[8][132];
    __shared__ unsigned Bh[8][68],  Bl[8][68];

    const int tid = threadIdx.x;
    const int lane = tid & 31;
    const int wid = tid >> 5;
    const int warp_m = wid >> 1;
    const int warp_n = wid & 1;
    const int tig = lane & 3;
    const int grp = lane >> 2;
    const int m0 = blockIdx.x * 128;
    const int n0 = blockIdx.y * 64;

    const int am0 = tid >> 2;
    const int am1 = am0 + 64;
    const int akp = (tid & 3) * 2;
    const int bn = tid & 63;
    const int bkh = tid >> 6;

    float acc[2][4][4];
#pragma unroll
    for (int mf = 0; mf < 2; ++mf)
#pragma unroll
        for (int nf = 0; nf < 4; ++nf)
#pragma unroll
            for (int j = 0; j < 4; ++j) acc[mf][nf][j] = 0.f;

    float4 va0 = make_float4(0.f, 0.f, 0.f, 0.f);
    float4 va1 = make_float4(0.f, 0.f, 0.f, 0.f);
    float pb0, pb1, pb2, pb3;
    if (m0 + am0 < M) va0 = *(const float4*)&A[(size_t)(m0 + am0) * K + akp * 2];
    if (m0 + am1 < M) va1 = *(const float4*)&A[(size_t)(m0 + am1) * K + akp * 2];
    pb0 = B[(size_t)(2 * bkh) * ldb + n0 + bn];
    pb1 = B[(size_t)(2 * bkh + 1) * ldb + n0 + bn];
    pb2 = B[(size_t)(2 * (bkh + 4)) * ldb + n0 + bn];
    pb3 = B[(size_t)(2 * (bkh + 4) + 1) * ldb + n0 + bn];

    for (int k0 = 0; k0 < K; k0 += 16) {
        {
            unsigned h, l;
            split2(va0.x, va0.y, h, l); Ah[akp][am0] = h;     Al[akp][am0] = l;
            split2(va0.z, va0.w, h, l); Ah[akp + 1][am0] = h; Al[akp + 1][am0] = l;
            split2(va1.x, va1.y, h, l); Ah[akp][am1] = h;     Al[akp][am1] = l;
            split2(va1.z, va1.w, h, l); Ah[akp + 1][am1] = h; Al[akp + 1][am1] = l;
            split2(pb0, pb1, h, l); Bh[bkh][bn] = h;     Bl[bkh][bn] = l;
            split2(pb2, pb3, h, l); Bh[bkh + 4][bn] = h; Bl[bkh + 4][bn] = l;
        }
        __syncthreads();

        if (k0 + 16 < K) {
            va0 = make_float4(0.f, 0.f, 0.f, 0.f);
            va1 = make_float4(0.f, 0.f, 0.f, 0.f);
            if (m0 + am0 < M) va0 = *(const float4*)&A[(size_t)(m0 + am0) * K + k0 + 16 + akp * 2];
            if (m0 + am1 < M) va1 = *(const float4*)&A[(size_t)(m0 + am1) * K + k0 + 16 + akp * 2];
            pb0 = B[(size_t)(k0 + 16 + 2 * bkh) * ldb + n0 + bn];
            pb1 = B[(size_t)(k0 + 16 + 2 * bkh + 1) * ldb + n0 + bn];
            pb2 = B[(size_t)(k0 + 16 + 2 * (bkh + 4)) * ldb + n0 + bn];
            pb3 = B[(size_t)(k0 + 16 + 2 * (bkh + 4) + 1) * ldb + n0 + bn];
        }

        unsigned ah[2][4], al_[2][4];
#pragma unroll
        for (int mf = 0; mf < 2; ++mf) {
            int mb = warp_m * 32 + mf * 16 + grp;
            ah[mf][0] = Ah[tig][mb];      al_[mf][0] = Al[tig][mb];
            ah[mf][1] = Ah[tig][mb + 8];  al_[mf][1] = Al[tig][mb + 8];
            ah[mf][2] = Ah[tig + 4][mb];      al_[mf][2] = Al[tig + 4][mb];
            ah[mf][3] = Ah[tig + 4][mb + 8];  al_[mf][3] = Al[tig + 4][mb + 8];
        }
#pragma unroll
        for (int nf = 0; nf < 4; ++nf) {
            int n = warp_n * 32 + nf * 8 + grp;
            unsigned bh0 = Bh[tig][n], bh1 = Bh[tig + 4][n];
            unsigned bl0 = Bl[tig][n], bl1 = Bl[tig + 4][n];
#pragma unroll
            for (int mf = 0; mf < 2; ++mf) {
                mma16(acc[mf][nf], ah[mf][0], ah[mf][1], ah[mf][2], ah[mf][3], bh0, bh1);
                mma16(acc[mf][nf], al_[mf][0], al_[mf][1], al_[mf][2], al_[mf][3], bh0, bh1);
                mma16(acc[mf][nf], ah[mf][0], ah[mf][1], ah[mf][2], ah[mf][3], bl0, bl1);
            }
        }
        __syncthreads();
    }

#pragma unroll
    for (int mf = 0; mf < 2; ++mf) {
        int r0 = m0 + warp_m * 32 + mf * 16 + grp;
        int r1 = r0 + 8;
#pragma unroll
        for (int nf = 0; nf < 4; ++nf) {
            int c = n0 + warp_n * 32 + nf * 8 + tig * 2;
            if (r0 < M)
                *(float2*)&C[(size_t)r0 * ldc + c] = make_float2(acc[mf][nf][0], acc[mf][nf][1]);
            if (r1 < M)
                *(float2*)&C[(size_t)r1 * ldc + c] = make_float2(acc[mf][nf][2], acc[mf][nf][3]);
        }
    }
}

// ---------------- CSR build ----------------
__global__ __launch_bounds__(256) void zero_cnt_kernel()
{
    int i = blockIdx.x * blockDim.x + threadIdx.x;
    if (i < N_NODES) g_cnt[i] = 0;
}
__global__ __launch_bounds__(256) void count_kernel(const int* __restrict__ ei)
{
    int e = blockIdx.x * blockDim.x + threadIdx.x;
    if (e < N_EDGES) atomicAdd(&g_cnt[ei[N_EDGES + e]], 1);
}
__global__ __launch_bounds__(256) void scan1_kernel()
{
    __shared__ int sh[256];
    int i = blockIdx.x * 256 + threadIdx.x;
    int v = (i < N_NODES) ? g_cnt[i] : 0;
    sh[threadIdx.x] = v;
    __syncthreads();
#pragma unroll
    for (int off = 1; off < 256; off <<= 1) {
        int t = 0;
        if (threadIdx.x >= off) t = sh[threadIdx.x - off];
        __syncthreads();
        if (threadIdx.x >= off) sh[threadIdx.x] += t;
        __syncthreads();
    }
    if (i < N_NODES) g_off[i + 1] = sh[threadIdx.x];
    if (threadIdx.x == 255) g_bsum[blockIdx.x] = sh[255];
    if (i == 0) g_off[0] = 0;
}
__global__ __launch_bounds__(256) void scan2_kernel(int nblocks)
{
    __shared__ int sh[256];
    int t = threadIdx.x;
    int v = (t < nblocks) ? g_bsum[t] : 0;
    sh[t] = v;
    __syncthreads();
#pragma unroll
    for (int off = 1; off < 256; off <<= 1) {
        int u = 0;
        if (t >= off) u = sh[t - off];
        __syncthreads();
        if (t >= off) sh[t] += u;
        __syncthreads();
    }
    if (t < nblocks) g_bsum[t] = sh[t] - v;    // exclusive
}
__global__ __launch_bounds__(256) void scan3_kernel()
{
    int i = blockIdx.x * 256 + threadIdx.x;
    if (i < N_NODES) {
        int v = g_off[i + 1] + g_bsum[blockIdx.x];
        g_off[i + 1] = v;
        if (i + 1 < N_NODES) g_fill[i + 1] = v;
        if (i == 0) g_fill[0] = 0;
    }
}
__global__ __launch_bounds__(256) void scatter_kernel(const int* __restrict__ ei)
{
    int e = blockIdx.x * blockDim.x + threadIdx.x;
    if (e >= N_EDGES) return;
    int s = ei[e], d = ei[N_EDGES + e];
    int pos = atomicAdd(&g_fill[d], 1);
    g_csrc[pos] = s;
}

// -------- gather attention: one warp per node, fused softmax+agg+relu ------
__global__ __launch_bounds__(256) void gat_gather_kernel(const float* __restrict__ b)
{
    const int warp = threadIdx.x >> 5, lane = threadIdx.x & 31;
    const int n = blockIdx.x * 8 + warp;
    if (n >= N_NODES) return;
    const unsigned FULL = 0xffffffffu;
    const int h0 = lane >> 3, h1 = 4 + (lane >> 3);

    float myasrc = 0.f, myadst = 0.f;
    if (lane < 8) {
        myasrc = g_asrc[n * 8 + lane];
        myadst = g_adst[n * 8 + lane];
    }
    float4 acc0 = make_float4(0.f, 0.f, 0.f, 0.f);
    float4 acc1 = make_float4(0.f, 0.f, 0.f, 0.f);
    float denom = 0.f;

    const int beg = g_off[n], end = g_off[n + 1];
    for (int i = beg; i < end; ++i) {
        int s = g_csrc[i];
        float w = 0.f;
        if (lane < 8) {
            w = expf(leaky(g_asrc[s * 8 + lane] + myadst));
            denom += w;
        }
        float al0 = __shfl_sync(FULL, w, h0);
        float al1 = __shfl_sync(FULL, w, h1);
        float4 v0 = *(const float4*)&g_h[(size_t)s * 256 + lane * 4];
        float4 v1 = *(const float4*)&g_h[(size_t)s * 256 + 128 + lane * 4];
        acc0.x += al0 * v0.x; acc0.y += al0 * v0.y;
        acc0.z += al0 * v0.z; acc0.w += al0 * v0.w;
        acc1.x += al1 * v1.x; acc1.y += al1 * v1.y;
        acc1.z += al1 * v1.z; acc1.w += al1 * v1.w;
    }
    // self loop
    {
        float w = 0.f;
        if (lane < 8) {
            w = expf(leaky(myasrc + myadst));
            denom += w;
        }
        float al0 = __shfl_sync(FULL, w, h0);
        float al1 = __shfl_sync(FULL, w, h1);
        float4 v0 = *(const float4*)&g_h[(size_t)n * 256 + lane * 4];
        float4 v1 = *(const float4*)&g_h[(size_t)n * 256 + 128 + lane * 4];
        acc0.x += al0 * v0.x; acc0.y += al0 * v0.y;
        acc0.z += al0 * v0.z; acc0.w += al0 * v0.w;
        acc1.x += al1 * v1.x; acc1.y += al1 * v1.y;
        acc1.z += al1 * v1.z; acc1.w += al1 * v1.w;
    }
    float inv0 = 1.f / __shfl_sync(FULL, denom, h0);
    float inv1 = 1.f / __shfl_sync(FULL, denom, h1);
    float4 bb0 = *(const float4*)&b[lane * 4];
    float4 bb1 = *(const float4*)&b[128 + lane * 4];
    float4 o0, o1;
    o0.x = fmaxf(acc0.x * inv0 + bb0.x, 0.f);
    o0.y = fmaxf(acc0.y * inv0 + bb0.y, 0.f);
    o0.z = fmaxf(acc0.z * inv0 + bb0.z, 0.f);
    o0.w = fmaxf(acc0.w * inv0 + bb0.w, 0.f);
    o1.x = fmaxf(acc1.x * inv1 + bb1.x, 0.f);
    o1.y = fmaxf(acc1.y * inv1 + bb1.y, 0.f);
    o1.z = fmaxf(acc1.z * inv1 + bb1.z, 0.f);
    o1.w = fmaxf(acc1.w * inv1 + bb1.w, 0.f);
    *(float4*)&g_x[(size_t)n * 256 + lane * 4] = o0;
    *(float4*)&g_x[(size_t)n * 256 + 128 + lane * 4] = o1;
}

// ---------------- pack Wcat = [Wp1_a | Wp1_b] : [256 x 64] ----------------
__global__ __launch_bounds__(256) void pack_wcat_kernel(const float* __restrict__ Wp1)
{
    int i = blockIdx.x * blockDim.x + threadIdx.x;
    if (i >= 256 * 64) return;
    int k = i >> 6, j = i & 63;
    g_wcat[i] = (j < 32) ? Wp1[k * 32 + j] : Wp1[(256 + k) * 32 + (j - 32)];
}

// ------- edge predictor: bf16-split tensor-core edge-MLP + exact combine ---
__global__ __launch_bounds__(128) void edge_pred_kernel(
    const int* __restrict__ ei, const float* __restrict__ edge_attr,
    const float* __restrict__ Wm1, const float* __restrict__ bm1,
    const float* __restrict__ Wm2, const float* __restrict__ bm2,
    const float* __restrict__ Wp1, const float* __restrict__ bp1,
    const float* __restrict__ Wp2, const float* __restrict__ bp2,
    float* __restrict__ out)
{
    __shared__ unsigned XH[16][66], XL[16][66];    // ping buffer
    __shared__ unsigned YH[16][66], YL[16][66];    // pong buffer
    __shared__ unsigned W1h[16][33], W1l[16][33];
    __shared__ unsigned W2h[16][33], W2l[16][33];
    __shared__ unsigned W3h[16][33], W3l[16][33];
    __shared__ int   sRow[64], sCol[64];
    __shared__ float sB[64];                       // bm1 | bm2

    const int tid = threadIdx.x;
    const int lane = tid & 31;
    const int wrp = tid >> 5;
    const int tig = lane & 3;
    const int grp = lane >> 2;
    const int e0 = blockIdx.x * 64;
    const int m0l = wrp * 16 + grp;                // local edge row (0..63)

    if (tid < 64) {
        sRow[tid] = ei[e0 + tid];
        sCol[tid] = ei[N_EDGES + e0 + tid];
    }
    if (tid < 32) { sB[tid] = bm1[tid]; sB[32 + tid] = bm2[tid]; }

    for (int i = tid; i < 512; i += 128) {
        int kp = i >> 5, n = i & 31;
        unsigned h, l;
        split2(Wm1[(2 * kp) * 32 + n], Wm1[(2 * kp + 1) * 32 + n], h, l);
        W1h[kp][n] = h; W1l[kp][n] = l;
        split2(Wm2[(2 * kp) * 32 + n], Wm2[(2 * kp + 1) * 32 + n], h, l);
        W2h[kp][n] = h; W2l[kp][n] = l;
        split2(Wp1[(512 + 2 * kp) * 32 + n], Wp1[(512 + 2 * kp + 1) * 32 + n], h, l);
        W3h[kp][n] = h; W3l[kp][n] = l;
    }
    for (int f = tid; f < 512; f += 128) {
        int e = f >> 3, q = f & 7;
        float4 v = *(const float4*)&edge_attr[(size_t)(e0 + e) * 32 + q * 4];
        unsigned h, l;
        split2(v.x, v.y, h, l); XH[2 * q][e] = h;     XL[2 * q][e] = l;
        split2(v.z, v.w, h, l); XH[2 * q + 1][e] = h; XL[2 * q + 1][e] = l;
    }
    __syncthreads();

    float acc[4][4];

#define EP_COMPUTE(IH, IL, WH, WL)                                            \
    {                                                                         \
        _Pragma("unroll")                                                     \
        for (int nf = 0; nf < 4; ++nf)                                        \
            _Pragma("unroll")                                                 \
            for (int j = 0; j < 4; ++j) acc[nf][j] = 0.f;                     \
        _Pragma("unroll")                                                     \
        for (int ks = 0; ks < 2; ++ks) {                                      \
            int kb = ks * 8;                                                  \
            unsigned a0 = IH[kb + tig][m0l],     l0 = IL[kb + tig][m0l];      \
            unsigned a1 = IH[kb + tig][m0l + 8], l1 = IL[kb + tig][m0l + 8];  \
            unsigned a2 = IH[kb + tig + 4][m0l],     l2 = IL[kb + tig + 4][m0l];     \
            unsigned a3 = IH[kb + tig + 4][m0l + 8], l3 = IL[kb + tig + 4][m0l + 8]; \
            _Pragma("unroll")                                                 \
            for (int nf = 0; nf < 4; ++nf) {                                  \
                int n = nf * 8 + grp;                                         \
                unsigned bh0 = WH[kb + tig][n], bh1 = WH[kb + tig + 4][n];    \
                unsigned bl0 = WL[kb + tig][n], bl1 = WL[kb + tig + 4][n];    \
                mma16(acc[nf], a0, a1, a2, a3, bh0, bh1);                     \
                mma16(acc[nf], l0, l1, l2, l3, bh0, bh1);                     \
                mma16(acc[nf], a0, a1, a2, a3, bl0, bl1);                     \
            }                                                                 \
        }                                                                     \
    }
#define EP_STORE(OH, OL, boff)                                                \
    {                                                                         \
        _Pragma("unroll")                                                     \
        for (int nf = 0; nf < 4; ++nf) {                                      \
            int j0 = nf * 8 + 2 * tig;                                        \
            int kp = nf * 4 + tig;                                            \
            float b0 = sB[boff + j0], b1 = sB[boff + j0 + 1];                 \
            float v0 = fmaxf(acc[nf][0] + b0, 0.f);                           \
            float v1 = fmaxf(acc[nf][1] + b1, 0.f);                           \
            float v2 = fmaxf(acc[nf][2] + b0, 0.f);                           \
            float v3 = fmaxf(acc[nf][3] + b1, 0.f);                           \
            unsigned h, l;                                                    \
            split2(v0, v1, h, l); OH[kp][m0l] = h;     OL[kp][m0l] = l;       \
            split2(v2, v3, h, l); OH[kp][m0l + 8] = h; OL[kp][m0l + 8] = l;   \
        }                                                                     \
    }

    EP_COMPUTE(XH, XL, W1h, W1l)
    EP_STORE(YH, YL, 0)
    __syncwarp();
    EP_COMPUTE(YH, YL, W2h, W2l)
    EP_STORE(XH, XL, 32)
    __syncwarp();
    EP_COMPUTE(XH, XL, W3h, W3l)

#undef EP_COMPUTE
#undef EP_STORE

    const int r0n = sRow[m0l],     c0n = sCol[m0l];
    const int r1n = sRow[m0l + 8], c1n = sCol[m0l + 8];
    float acc_r0 = 0.f, acc_r1 = 0.f;
#pragma unroll
    for (int nf = 0; nf < 4; ++nf) {
        int j0 = nf * 8 + 2 * tig;
        float2 pa0 = *(const float2*)&g_p[(size_t)r0n * 64 + j0];
        float2 pb0 = *(const float2*)&g_p[(size_t)c0n * 64 + 32 + j0];
        float2 pa1 = *(const float2*)&g_p[(size_t)r1n * 64 + j0];
        float2 pb1 = *(const float2*)&g_p[(size_t)c1n * 64 + 32 + j0];
        float b0 = bp1[j0], b1 = bp1[j0 + 1];
        float w0 = Wp2[j0], w1 = Wp2[j0 + 1];
        float h;
        h = acc[nf][0] + pa0.x + pb0.x + b0; acc_r0 += fmaxf(h, 0.f) * w0;
        h = acc[nf][1] + pa0.y + pb0.y + b1; acc_r0 += fmaxf(h, 0.f) * w1;
        h = acc[nf][2] + pa1.x + pb1.x + b0; acc_r1 += fmaxf(h, 0.f) * w0;
        h = acc[nf][3] + pa1.y + pb1.y + b1; acc_r1 += fmaxf(h, 0.f) * w1;
    }
    acc_r0 += __shfl_xor_sync(0xffffffffu, acc_r0, 1);
    acc_r0 += __shfl_xor_sync(0xffffffffu, acc_r0, 2);
    acc_r1 += __shfl_xor_sync(0xffffffffu, acc_r1, 1);
    acc_r1 += __shfl_xor_sync(0xffffffffu, acc_r1, 2);
    if (tig == 0) {
        float bias2 = bp2[0];
        out[e0 + m0l]     = acc_r0 + bias2;
        out[e0 + m0l + 8] = acc_r1 + bias2;
    }
}

// ---------------- host ----------------
extern "C" void kernel_launch(void* const* d_in, const int* in_sizes, int n_in,
                              void* d_out, int out_size)
{
    const float* x   = (const float*)d_in[0];
    const int*   ei  = (const int*)d_in[1];
    const float* ea  = (const float*)d_in[2];
    const float* W1  = (const float*)d_in[3];
    const float* as1 = (const float*)d_in[4];
    const float* ad1 = (const float*)d_in[5];
    const float* b1  = (const float*)d_in[6];
    const float* W2  = (const float*)d_in[7];
    const float* as2 = (const float*)d_in[8];
    const float* ad2 = (const float*)d_in[9];
    const float* b2  = (const float*)d_in[10];
    const float* Wm1 = (const float*)d_in[11];
    const float* bm1 = (const float*)d_in[12];
    const float* Wm2 = (const float*)d_in[13];
    const float* bm2 = (const float*)d_in[14];
    const float* Wp1 = (const float*)d_in[15];
    const float* bp1 = (const float*)d_in[16];
    const float* Wp2 = (const float*)d_in[17];
    const float* bp2 = (const float*)d_in[18];
    float* out = (float*)d_out;

    float *ph = nullptr, *px = nullptr, *pw = nullptr, *pp = nullptr;
    cudaGetSymbolAddress((void**)&ph, g_h);
    cudaGetSymbolAddress((void**)&px, g_x);
    cudaGetSymbolAddress((void**)&pw, g_wcat);
    cudaGetSymbolAddress((void**)&pp, g_p);

    const int EB  = (N_EDGES + 255) / 256;
    const int NB  = (N_NODES + 255) / 256;
    const int NWB = (N_NODES + 7) / 8;

    // ---- CSR build (once; reused by both layers) ----
    zero_cnt_kernel<<<NB, 256>>>();
    count_kernel<<<EB, 256>>>(ei);
    scan1_kernel<<<NB, 256>>>();
    scan2_kernel<<<1, 256>>>(NB);
    scan3_kernel<<<NB, 256>>>();
    scatter_kernel<<<EB, 256>>>(ei);

    for (int layer = 0; layer < 2; ++layer) {
        const float* X   = layer ? px : x;
        const int    K   = layer ? 256 : 128;
        const float* W   = layer ? W2 : W1;
        const float* as_ = layer ? as2 : as1;
        const float* ad_ = layer ? ad2 : ad1;
        const float* b_  = layer ? b2 : b1;

        tc_gemm128_kernel<<<dim3(391, 2), 256>>>(X, W, ph, N_NODES, K, 256, 256, as_, ad_);
        gat_gather_kernel<<<NWB, 256>>>(b_);
    }
    pack_wcat_kernel<<<64, 256>>>(Wp1);
    tc_gemm_kernel<<<dim3(391, 1), 256>>>(px, pw, pp, N_NODES, 256, 64, 64);
    edge_pred_kernel<<<N_EDGES / 64, 128>>>(ei, ea,
                                            Wm1, bm1, Wm2, bm2,
                                            Wp1, bp1, Wp2, bp2, out);
}